// round 2
// baseline (speedup 1.0000x reference)
#include <cuda_runtime.h>

// ---------------------------------------------------------------------------
// LinearAttention  B=8, N=4096, D_IN=D_OUT=1024  (all fp32)
//   q = x @ Wq^T + bq ; k = x @ Wk^T + bk ; v = x @ Wv^T + bv
//   attn[b] = softmax_rows( q[b]^T @ k[b] )      [1024 x 1024]
//   out[b]  = v[b] @ attn[b]                     [4096 x 1024]
// All GEMMs via one templated 128x128x16 fp32 tile kernel using packed
// fma.rn.f32x2 (FFMA2) — full-rate fp32 on sm_103a (3-reg FFMA is half rate).
// ---------------------------------------------------------------------------

#define B_   8
#define N_   4096
#define D_   1024

__device__ float g_q[(size_t)B_ * N_ * D_];     // 128 MB
__device__ float g_k[(size_t)B_ * N_ * D_];     // 128 MB
__device__ float g_v[(size_t)B_ * N_ * D_];     // 128 MB
__device__ float g_attn[(size_t)B_ * D_ * D_];  //  32 MB

__device__ __forceinline__ unsigned long long pack2(float x, float y) {
    unsigned long long r;
    asm("mov.b64 %0, {%1, %2};" : "=l"(r) : "f"(x), "f"(y));
    return r;
}
__device__ __forceinline__ void fma2(unsigned long long& c,
                                     unsigned long long a,
                                     unsigned long long b) {
    // packed (c.x += a.x*b.x, c.y += a.y*b.y)
    asm("fma.rn.f32x2 %0, %1, %2, %0;" : "+l"(c) : "l"(a), "l"(b));
}
__device__ __forceinline__ void unpack2(unsigned long long v, float& x, float& y) {
    asm("mov.b64 {%0, %1}, %2;" : "=f"(x), "=f"(y) : "l"(v));
}

// A_MK: A stored [M,K] row-major (k contiguous)  -> transpose-load into smem
//       else A stored [K,M] (m contiguous)       -> direct load
// B_NK: B stored [N,K] row-major (k contiguous)  -> transpose-load
//       else B stored [K,N] (n contiguous)       -> direct load
// C is [M,N] row-major (ldc = Nn). All of M,Nn multiples of 128, K of 16.
template <bool A_MK, bool B_NK, bool HAS_BIAS>
__global__ void __launch_bounds__(256)
gemm_kernel(const float* __restrict__ A, const float* __restrict__ Bm,
            const float* __restrict__ bias, float* __restrict__ C,
            int M, int Nn, int K,
            size_t aB, size_t bB, size_t cB) {
    __shared__ float As[16][132];
    __shared__ float Bs[16][132];

    const int tid = threadIdx.x;
    const float* Ab = A + (size_t)blockIdx.z * aB;
    const float* Bb = Bm + (size_t)blockIdx.z * bB;
    float* Cb = C + (size_t)blockIdx.z * cB;
    const int m0 = blockIdx.y * 128;
    const int n0 = blockIdx.x * 128;

    const int tx = tid & 15, ty = tid >> 4;
    const int rm = ty * 8, cn = tx * 8;

    unsigned long long acc[8][4];
#pragma unroll
    for (int i = 0; i < 8; ++i)
#pragma unroll
        for (int j = 0; j < 4; ++j) acc[i][j] = 0ull;

    float4 ra[2], rb[2];

    auto loadA = [&](int kt, float4* dst) {
#pragma unroll
        for (int it = 0; it < 2; ++it) {
            int idx = tid + (it << 8);
            if (A_MK) {
                int mm = idx >> 2, kk = (idx & 3) << 2;
                dst[it] = *reinterpret_cast<const float4*>(
                    Ab + (size_t)(m0 + mm) * K + kt * 16 + kk);
            } else {
                int kk = idx >> 5, mm = (idx & 31) << 2;
                dst[it] = *reinterpret_cast<const float4*>(
                    Ab + (size_t)(kt * 16 + kk) * M + m0 + mm);
            }
        }
    };
    auto storeA = [&](const float4* v) {
#pragma unroll
        for (int it = 0; it < 2; ++it) {
            int idx = tid + (it << 8);
            if (A_MK) {
                int mm = idx >> 2, kk = (idx & 3) << 2;
                As[kk + 0][mm] = v[it].x;
                As[kk + 1][mm] = v[it].y;
                As[kk + 2][mm] = v[it].z;
                As[kk + 3][mm] = v[it].w;
            } else {
                int kk = idx >> 5, mm = (idx & 31) << 2;
                *reinterpret_cast<float4*>(&As[kk][mm]) = v[it];
            }
        }
    };
    auto loadB = [&](int kt, float4* dst) {
#pragma unroll
        for (int it = 0; it < 2; ++it) {
            int idx = tid + (it << 8);
            if (B_NK) {
                int nn = idx >> 2, kk = (idx & 3) << 2;
                dst[it] = *reinterpret_cast<const float4*>(
                    Bb + (size_t)(n0 + nn) * K + kt * 16 + kk);
            } else {
                int kk = idx >> 5, nn = (idx & 31) << 2;
                dst[it] = *reinterpret_cast<const float4*>(
                    Bb + (size_t)(kt * 16 + kk) * Nn + n0 + nn);
            }
        }
    };
    auto storeB = [&](const float4* v) {
#pragma unroll
        for (int it = 0; it < 2; ++it) {
            int idx = tid + (it << 8);
            if (B_NK) {
                int nn = idx >> 2, kk = (idx & 3) << 2;
                Bs[kk + 0][nn] = v[it].x;
                Bs[kk + 1][nn] = v[it].y;
                Bs[kk + 2][nn] = v[it].z;
                Bs[kk + 3][nn] = v[it].w;
            } else {
                int kk = idx >> 5, nn = (idx & 31) << 2;
                *reinterpret_cast<float4*>(&Bs[kk][nn]) = v[it];
            }
        }
    };
    auto compute = [&]() {
#pragma unroll
        for (int kk = 0; kk < 16; ++kk) {
            float4 a0 = *reinterpret_cast<const float4*>(&As[kk][rm]);
            float4 a1 = *reinterpret_cast<const float4*>(&As[kk][rm + 4]);
            const unsigned long long* bp =
                reinterpret_cast<const unsigned long long*>(&Bs[kk][cn]);
            unsigned long long b2[4] = {bp[0], bp[1], bp[2], bp[3]};
            float av[8] = {a0.x, a0.y, a0.z, a0.w, a1.x, a1.y, a1.z, a1.w};
#pragma unroll
            for (int i = 0; i < 8; ++i) {
                unsigned long long pa = pack2(av[i], av[i]);
#pragma unroll
                for (int j = 0; j < 4; ++j) fma2(acc[i][j], pa, b2[j]);
            }
        }
    };

    // prologue: tile 0 straight into smem
    loadA(0, ra);
    loadB(0, rb);
    storeA(ra);
    storeB(rb);
    __syncthreads();

    const int nt = K >> 4;
    for (int t = 0; t < nt; ++t) {
        const bool has_next = (t + 1) < nt;
        if (has_next) {  // prefetch next tile into registers (hides GMEM latency)
            loadA(t + 1, ra);
            loadB(t + 1, rb);
        }
        compute();
        if (has_next) {
            __syncthreads();
            storeA(ra);
            storeB(rb);
            __syncthreads();
        }
    }

    float bvs[8];
    if (HAS_BIAS) {
        float4 b0 = *reinterpret_cast<const float4*>(bias + n0 + cn);
        float4 b1 = *reinterpret_cast<const float4*>(bias + n0 + cn + 4);
        bvs[0] = b0.x; bvs[1] = b0.y; bvs[2] = b0.z; bvs[3] = b0.w;
        bvs[4] = b1.x; bvs[5] = b1.y; bvs[6] = b1.z; bvs[7] = b1.w;
    }
#pragma unroll
    for (int i = 0; i < 8; ++i) {
        float o[8];
#pragma unroll
        for (int j = 0; j < 4; ++j) unpack2(acc[i][j], o[2 * j], o[2 * j + 1]);
        if (HAS_BIAS) {
#pragma unroll
            for (int j = 0; j < 8; ++j) o[j] += bvs[j];
        }
        float4* cp = reinterpret_cast<float4*>(
            Cb + (size_t)(m0 + rm + i) * Nn + n0 + cn);
        cp[0] = make_float4(o[0], o[1], o[2], o[3]);
        cp[1] = make_float4(o[4], o[5], o[6], o[7]);
    }
}

// one block per row of 1024; rows = B*D = 8192
__global__ void __launch_bounds__(256) softmax_kernel(float* __restrict__ attn) {
    float* p = attn + (size_t)blockIdx.x * 1024;
    const int t = threadIdx.x;
    const int lane = t & 31, wid = t >> 5;
    __shared__ float red[8];

    float v[4];
#pragma unroll
    for (int i = 0; i < 4; ++i) v[i] = p[t + (i << 8)];

    float m = fmaxf(fmaxf(v[0], v[1]), fmaxf(v[2], v[3]));
#pragma unroll
    for (int o = 16; o; o >>= 1) m = fmaxf(m, __shfl_xor_sync(0xffffffffu, m, o));
    if (lane == 0) red[wid] = m;
    __syncthreads();
    if (t < 32) {
        float x = (t < 8) ? red[t] : -3.4e38f;
#pragma unroll
        for (int o = 4; o; o >>= 1) x = fmaxf(x, __shfl_xor_sync(0xffffffffu, x, o));
        if (t == 0) red[0] = x;
    }
    __syncthreads();
    m = red[0];
    __syncthreads();

    float s = 0.f;
#pragma unroll
    for (int i = 0; i < 4; ++i) {
        v[i] = expf(v[i] - m);
        s += v[i];
    }
#pragma unroll
    for (int o = 16; o; o >>= 1) s += __shfl_xor_sync(0xffffffffu, s, o);
    if (lane == 0) red[wid] = s;
    __syncthreads();
    if (t < 32) {
        float x = (t < 8) ? red[t] : 0.f;
#pragma unroll
        for (int o = 4; o; o >>= 1) x += __shfl_xor_sync(0xffffffffu, x, o);
        if (t == 0) red[0] = x;
    }
    __syncthreads();
    const float inv = 1.0f / red[0];
#pragma unroll
    for (int i = 0; i < 4; ++i) p[t + (i << 8)] = v[i] * inv;
}

extern "C" void kernel_launch(void* const* d_in, const int* in_sizes, int n_in,
                              void* d_out, int out_size) {
    const float* x  = (const float*)d_in[0];
    const float* Wq = (const float*)d_in[1];
    const float* bq = (const float*)d_in[2];
    const float* Wk = (const float*)d_in[3];
    const float* bk = (const float*)d_in[4];
    const float* Wv = (const float*)d_in[5];
    const float* bv = (const float*)d_in[6];
    float* out = (float*)d_out;

    float *q, *k, *v, *attn;
    cudaGetSymbolAddress((void**)&q, g_q);
    cudaGetSymbolAddress((void**)&k, g_k);
    cudaGetSymbolAddress((void**)&v, g_v);
    cudaGetSymbolAddress((void**)&attn, g_attn);

    const dim3 blk(256);

    // QKV projections: C[32768,1024] = X[32768,1024] @ W[1024,1024]^T + b
    const dim3 gq(1024 / 128, (B_ * N_) / 128, 1);
    gemm_kernel<true, true, true><<<gq, blk>>>(x, Wq, bq, q, B_ * N_, D_, D_, 0, 0, 0);
    gemm_kernel<true, true, true><<<gq, blk>>>(x, Wk, bk, k, B_ * N_, D_, D_, 0, 0, 0);
    gemm_kernel<true, true, true><<<gq, blk>>>(x, Wv, bv, v, B_ * N_, D_, D_, 0, 0, 0);

    // attn[b] = q[b]^T @ k[b]  (M=N=1024, K=4096), batched over z
    const dim3 ga(1024 / 128, 1024 / 128, B_);
    gemm_kernel<false, false, false><<<ga, blk>>>(
        q, k, nullptr, attn, D_, D_, N_,
        (size_t)N_ * D_, (size_t)N_ * D_, (size_t)D_ * D_);

    // row softmax over 8192 rows of 1024
    softmax_kernel<<<B_ * D_, 256>>>(attn);

    // out[b] = v[b] @ attn[b]  (M=4096, K=1024, N=1024)
    const dim3 go(1024 / 128, N_ / 128, B_);
    gemm_kernel<true, false, false><<<go, blk>>>(
        v, attn, nullptr, out, N_, D_, D_,
        (size_t)N_ * D_, (size_t)D_ * D_, (size_t)N_ * D_);
}

// round 4
// speedup vs baseline: 1.0542x; 1.0542x over previous
#include <cuda_runtime.h>
#include <cstdint>

#define B_   8
#define N_   4096
#define D_   1024

// scratch (device globals; no allocations allowed)
__device__ float g_qt[(size_t)B_ * D_ * N_];     // q^T per batch [b][e][n]
__device__ float g_kt[(size_t)B_ * D_ * N_];     // k^T per batch [b][e][n]
__device__ float g_v [(size_t)B_ * N_ * D_];     // v natural [b*n][e]
__device__ float g_attn [(size_t)B_ * D_ * D_];  // attn [b][e][f]
__device__ float g_attnT[(size_t)B_ * D_ * D_];  // attn^T [b][f][e]

__device__ __forceinline__ uint32_t tf32_hi(float x) {
    uint32_t r;
    asm("cvt.rna.tf32.f32 %0, %1;" : "=r"(r) : "f"(x));
    return r;
}

__device__ __forceinline__ void mma8(float* c, const uint32_t* a,
                                     const uint32_t* b) {
    asm("mma.sync.aligned.m16n8k8.row.col.f32.tf32.tf32.f32 "
        "{%0,%1,%2,%3}, {%4,%5,%6,%7}, {%8,%9}, {%0,%1,%2,%3};"
        : "+f"(c[0]), "+f"(c[1]), "+f"(c[2]), "+f"(c[3])
        : "r"(a[0]), "r"(a[1]), "r"(a[2]), "r"(a[3]), "r"(b[0]), "r"(b[1]));
}

// ---------------------------------------------------------------------------
// TF32 (3x split) mma.sync GEMM: C[M,N] = A[M,K] * B[N,K]^T (+bias)
// Both A and B K-major. CTA tile 128x128, K-stage 32, double-buffered smem
// in FRAGMENT order:
//   A: [stage][s(4)][mt(8)][lane(32)][reg(4)]  (16KB/stage)
//   B: [stage][s(4)][nt(16)][lane(32)][reg(2)] (16KB/stage)
// 8 warps, warp grid 2(M) x 4(N), warp tile 64x32.
// ---------------------------------------------------------------------------
constexpr int SMEM_BYTES = 2 * (16384 + 16384);  // 64 KB

template <bool TRANS_OUT, bool HAS_BIAS>
__global__ void __launch_bounds__(256)
mma_gemm(const float* __restrict__ A, const float* __restrict__ Bm,
         const float* __restrict__ bias, float* __restrict__ C,
         int M, int Nn, int K, size_t aB, size_t bB, size_t cB) {
    extern __shared__ float sm[];
    float* As = sm;          // 2 * 4096 floats
    float* Bs = sm + 8192;   // 2 * 4096 floats

    const int tid = threadIdx.x;
    const int lane = tid & 31, wid = tid >> 5;
    const int wm = wid & 1, wn = wid >> 1;   // warp grid 2 x 4
    const float* Ab = A + (size_t)blockIdx.z * aB;
    const float* Bb = Bm + (size_t)blockIdx.z * bB;
    const int m0 = blockIdx.y * 128;
    const int n0 = blockIdx.x * 128;

    float acc[4][4][4];
#pragma unroll
    for (int i = 0; i < 4; ++i)
#pragma unroll
        for (int j = 0; j < 4; ++j)
#pragma unroll
            for (int e = 0; e < 4; ++e) acc[i][j][e] = 0.f;

    float4 ra[4], rb[4];
    auto ldg = [&](int kt) {
#pragma unroll
        for (int it = 0; it < 4; ++it) {
            int idx = tid + (it << 8);
            int mm = idx >> 3, k4 = idx & 7;  // 4 consecutive k at k4*4
            ra[it] = *reinterpret_cast<const float4*>(
                Ab + (size_t)(m0 + mm) * K + kt * 32 + (k4 << 2));
            rb[it] = *reinterpret_cast<const float4*>(
                Bb + (size_t)(n0 + mm) * K + kt * 32 + (k4 << 2));
        }
    };
    auto sts = [&](int buf) {
        float* Ad = As + buf * 4096;
        float* Bd = Bs + buf * 4096;
#pragma unroll
        for (int it = 0; it < 4; ++it) {
            int idx = tid + (it << 8);
            int mm = idx >> 3, k4 = idx & 7;
            int s = k4 >> 1, kh = k4 & 1;  // k-step, kc>=4 half
            {   // A fragment scatter: lane = (mm&7)*4 + c ; reg = ((mm>>3)&1)+2*kh
                int mt = mm >> 4, r = mm & 7;
                int reg = ((mm >> 3) & 1) + (kh << 1);
                int base = (((s << 3) + mt) << 5) + (r << 2);  // lane base
                float v[4] = {ra[it].x, ra[it].y, ra[it].z, ra[it].w};
#pragma unroll
                for (int c = 0; c < 4; ++c) Ad[((base + c) << 2) + reg] = v[c];
            }
            {   // B fragment scatter: lane = (mm&7)*4 + c ; reg = kh
                int nt = mm >> 3, nr = mm & 7;
                int base = (((s << 4) + nt) << 5) + (nr << 2);
                float v[4] = {rb[it].x, rb[it].y, rb[it].z, rb[it].w};
#pragma unroll
                for (int c = 0; c < 4; ++c) Bd[((base + c) << 1) + kh] = v[c];
            }
        }
    };
    auto compute = [&](int buf) {
        const float* Ad = As + buf * 4096;
        const float* Bd = Bs + buf * 4096;
#pragma unroll
        for (int s = 0; s < 4; ++s) {
            uint32_t ah[4][4], al[4][4], bh[4][2], bl[4][2];
#pragma unroll
            for (int i = 0; i < 4; ++i) {
                float4 a = *reinterpret_cast<const float4*>(
                    Ad + (((((s << 3) + (wm << 2) + i) << 5) + lane) << 2));
                float av[4] = {a.x, a.y, a.z, a.w};
#pragma unroll
                for (int e = 0; e < 4; ++e) {
                    uint32_t h = tf32_hi(av[e]);
                    ah[i][e] = h;
                    al[i][e] = __float_as_uint(av[e] - __uint_as_float(h));
                }
            }
#pragma unroll
            for (int j = 0; j < 4; ++j) {
                float2 b = *reinterpret_cast<const float2*>(
                    Bd + (((((s << 4) + (wn << 2) + j) << 5) + lane) << 1));
                float bv[2] = {b.x, b.y};
#pragma unroll
                for (int e = 0; e < 2; ++e) {
                    uint32_t h = tf32_hi(bv[e]);
                    bh[j][e] = h;
                    bl[j][e] = __float_as_uint(bv[e] - __uint_as_float(h));
                }
            }
#pragma unroll
            for (int i = 0; i < 4; ++i)
#pragma unroll
                for (int j = 0; j < 4; ++j) {
                    mma8(acc[i][j], ah[i], bh[j]);
                    mma8(acc[i][j], ah[i], bl[j]);
                    mma8(acc[i][j], al[i], bh[j]);
                }
        }
    };

    ldg(0);
    sts(0);
    __syncthreads();
    const int nt = K >> 5;
    for (int t = 0; t < nt; ++t) {
        if (t + 1 < nt) ldg(t + 1);
        compute(t & 1);
        if (t + 1 < nt) {
            __syncthreads();
            sts((t + 1) & 1);
            __syncthreads();
        }
    }

    // epilogue: acc[i][j] -> rows wm*64+i*16+{r, r+8}, cols wn*32+j*8+{2c,2c+1}
    const int r = lane >> 2, cq = (lane & 3) << 1;
#pragma unroll
    for (int i = 0; i < 4; ++i) {
#pragma unroll
        for (int j = 0; j < 4; ++j) {
            const int row = m0 + (wm << 6) + (i << 4) + r;
            const int col = n0 + (wn << 5) + (j << 3) + cq;
            float o0 = acc[i][j][0], o1 = acc[i][j][1];
            float o2 = acc[i][j][2], o3 = acc[i][j][3];
            if (HAS_BIAS) {
                float b0 = bias[col], b1 = bias[col + 1];
                o0 += b0; o1 += b1; o2 += b0; o3 += b1;
            }
            if (TRANS_OUT) {
                // C^T per batch: C[b][col][row_within_batch], ld = 4096
                const int bz = row >> 12;
                const int mr = row & 4095;
                float* base = C + (size_t)bz * (size_t)Nn * 4096 + mr;
                base[(size_t)col * 4096] = o0;
                base[(size_t)(col + 1) * 4096] = o1;
                base[(size_t)col * 4096 + 8] = o2;
                base[(size_t)(col + 1) * 4096 + 8] = o3;
            } else {
                float* Cb = C + (size_t)blockIdx.z * cB;
                *reinterpret_cast<float2*>(Cb + (size_t)row * Nn + col) =
                    make_float2(o0, o1);
                *reinterpret_cast<float2*>(Cb + (size_t)(row + 8) * Nn + col) =
                    make_float2(o2, o3);
            }
        }
    }
}

// ---------------------------------------------------------------------------
// softmax over rows of 1024 (in place), one block per row
// ---------------------------------------------------------------------------
__global__ void __launch_bounds__(256) softmax_kernel(float* __restrict__ attn) {
    float* p = attn + (size_t)blockIdx.x * 1024;
    const int t = threadIdx.x;
    const int lane = t & 31, wid = t >> 5;
    __shared__ float red[8];

    float v[4];
#pragma unroll
    for (int i = 0; i < 4; ++i) v[i] = p[t + (i << 8)];

    float m = fmaxf(fmaxf(v[0], v[1]), fmaxf(v[2], v[3]));
#pragma unroll
    for (int o = 16; o; o >>= 1) m = fmaxf(m, __shfl_xor_sync(0xffffffffu, m, o));
    if (lane == 0) red[wid] = m;
    __syncthreads();
    if (t < 32) {
        float x = (t < 8) ? red[t] : -3.4e38f;
#pragma unroll
        for (int o = 4; o; o >>= 1) x = fmaxf(x, __shfl_xor_sync(0xffffffffu, x, o));
        if (t == 0) red[0] = x;
    }
    __syncthreads();
    m = red[0];
    __syncthreads();

    float s = 0.f;
#pragma unroll
    for (int i = 0; i < 4; ++i) {
        v[i] = expf(v[i] - m);
        s += v[i];
    }
#pragma unroll
    for (int o = 16; o; o >>= 1) s += __shfl_xor_sync(0xffffffffu, s, o);
    if (lane == 0) red[wid] = s;
    __syncthreads();
    if (t < 32) {
        float x = (t < 8) ? red[t] : 0.f;
#pragma unroll
        for (int o = 4; o; o >>= 1) x += __shfl_xor_sync(0xffffffffu, x, o);
        if (t == 0) red[0] = x;
    }
    __syncthreads();
    const float inv = 1.0f / red[0];
#pragma unroll
    for (int i = 0; i < 4; ++i) p[t + (i << 8)] = v[i] * inv;
}

// 1024x1024 transpose per batch, 32x32 tiles
__global__ void __launch_bounds__(256)
transpose_kernel(const float* __restrict__ in, float* __restrict__ out) {
    __shared__ float t[32][33];
    const float* ib = in + (size_t)blockIdx.z * 1024 * 1024;
    float* ob = out + (size_t)blockIdx.z * 1024 * 1024;
    const int x = blockIdx.x * 32 + threadIdx.x;
    const int y0 = blockIdx.y * 32;
#pragma unroll
    for (int j = threadIdx.y; j < 32; j += 8)
        t[j][threadIdx.x] = ib[(size_t)(y0 + j) * 1024 + x];
    __syncthreads();
    const int xo = blockIdx.y * 32 + threadIdx.x;
#pragma unroll
    for (int j = threadIdx.y; j < 32; j += 8)
        ob[(size_t)(blockIdx.x * 32 + j) * 1024 + xo] = t[threadIdx.x][j];
}

extern "C" void kernel_launch(void* const* d_in, const int* in_sizes, int n_in,
                              void* d_out, int out_size) {
    const float* x  = (const float*)d_in[0];
    const float* Wq = (const float*)d_in[1];
    const float* bq = (const float*)d_in[2];
    const float* Wk = (const float*)d_in[3];
    const float* bk = (const float*)d_in[4];
    const float* Wv = (const float*)d_in[5];
    const float* bv = (const float*)d_in[6];
    float* out = (float*)d_out;

    float *qt, *kt, *v, *attn, *attnT;
    cudaGetSymbolAddress((void**)&qt, g_qt);
    cudaGetSymbolAddress((void**)&kt, g_kt);
    cudaGetSymbolAddress((void**)&v, g_v);
    cudaGetSymbolAddress((void**)&attn, g_attn);
    cudaGetSymbolAddress((void**)&attnT, g_attnT);

    cudaFuncSetAttribute(mma_gemm<true, true>,
                         cudaFuncAttributeMaxDynamicSharedMemorySize, SMEM_BYTES);
    cudaFuncSetAttribute(mma_gemm<false, true>,
                         cudaFuncAttributeMaxDynamicSharedMemorySize, SMEM_BYTES);
    cudaFuncSetAttribute(mma_gemm<false, false>,
                         cudaFuncAttributeMaxDynamicSharedMemorySize, SMEM_BYTES);

    const dim3 blk(256);

    // projections: [32768,1024] = x @ W^T + b ; q,k written transposed per batch
    const dim3 gp(1024 / 128, (B_ * N_) / 128, 1);
    mma_gemm<true, true><<<gp, blk, SMEM_BYTES>>>(x, Wq, bq, qt,
                                                  B_ * N_, D_, D_, 0, 0, 0);
    mma_gemm<true, true><<<gp, blk, SMEM_BYTES>>>(x, Wk, bk, kt,
                                                  B_ * N_, D_, D_, 0, 0, 0);
    mma_gemm<false, true><<<gp, blk, SMEM_BYTES>>>(x, Wv, bv, v,
                                                   B_ * N_, D_, D_, 0, 0, 0);

    // attn[b][e][f] = sum_n qt[b][e][n] * kt[b][f][n]   (M=N=1024, K=4096)
    const dim3 ga(1024 / 128, 1024 / 128, B_);
    mma_gemm<false, false><<<ga, blk, SMEM_BYTES>>>(
        qt, kt, nullptr, attn, D_, D_, N_,
        (size_t)D_ * N_, (size_t)D_ * N_, (size_t)D_ * D_);

    softmax_kernel<<<B_ * D_, 256>>>(attn);
    transpose_kernel<<<dim3(32, 32, B_), dim3(32, 8)>>>(attn, attnT);

    // out[b][n][f] = sum_e v[b][n][e] * attnT[b][f][e]  (M=4096, N=1024, K=1024)
    const dim3 go(1024 / 128, N_ / 128, B_);
    mma_gemm<false, false><<<go, blk, SMEM_BYTES>>>(
        v, attnT, nullptr, out, N_, D_, D_,
        (size_t)N_ * D_, (size_t)D_ * D_, (size_t)N_ * D_);
}

// round 5
// speedup vs baseline: 1.7014x; 1.6138x over previous
#include <cuda_runtime.h>
#include <cstdint>

#define B_   8
#define N_   4096
#define D_   1024

// scratch (device globals; no allocations allowed)
__device__ float g_v [(size_t)B_ * N_ * D_];   // v projection      128 MB
__device__ float g_G [(size_t)B_ * D_ * D_];   // G = x^T x          32 MB
__device__ float g_T1[(size_t)B_ * D_ * D_];   // T1 = G Wk^T        32 MB
__device__ float g_L [(size_t)B_ * D_ * D_];   // logits -> attn     32 MB
__device__ float g_s [(size_t)B_ * D_];        // s = x^T 1
__device__ float g_u [(size_t)B_ * D_];        // u = Wq s
__device__ float g_w [(size_t)B_ * D_];        // w' = Wk s + N*bk

__device__ __forceinline__ uint32_t tf32_hi(float x) {
    uint32_t r;
    asm("cvt.rna.tf32.f32 %0, %1;" : "=r"(r) : "f"(x));
    return r;
}
__device__ __forceinline__ void mma8(float* c, const uint32_t* a,
                                     const uint32_t* b) {
    asm("mma.sync.aligned.m16n8k8.row.col.f32.tf32.tf32.f32 "
        "{%0,%1,%2,%3}, {%4,%5,%6,%7}, {%8,%9}, {%0,%1,%2,%3};"
        : "+f"(c[0]), "+f"(c[1]), "+f"(c[2]), "+f"(c[3])
        : "r"(a[0]), "r"(a[1]), "r"(a[2]), "r"(a[3]), "r"(b[0]), "r"(b[1]));
}

// ---------------------------------------------------------------------------
// TF32 (3x split) mma.sync GEMM: C[M,N] = A * B^T  (K-contracted) (+bias)
//   A_KM=false: A stored [M,K] (k contig), true: [K,M] (m contig)
//   B_KN=false: B stored [N,K] (k contig), true: [K,N] (n contig)
// CTA tile 128x128, 512 threads, 16 warps (grid 4x4), warp tile 32x32.
// K-stage 32, double-buffered fragment-order SMEM, ONE syncthreads/stage.
// Fragment layout (padded to avoid bank conflicts):
//   A: idx = s*1060 + mt*132 + lane*4 + reg   (s<4, mt<8, reg<4)
//   B: idx = s*1058 + nt*66  + lane*2 + reg   (nt<16, reg<2)
// ---------------------------------------------------------------------------
constexpr int ASTG = 4240, BSTG = 4232;
constexpr int BOFF = 2 * ASTG;                         // floats
constexpr int SMEM_BYTES = (2 * ASTG + 2 * BSTG) * 4;  // 67,776 B

template <bool A_KM, bool B_KN, bool HAS_BIAS>
__global__ void __launch_bounds__(512, 1)
mma_gemm(const float* __restrict__ A, const float* __restrict__ Bm,
         const float* __restrict__ bias, float* __restrict__ C,
         int M, int Nn, int K, int lda, int ldb,
         size_t aB, size_t bB, size_t cB) {
    extern __shared__ float sm[];
    const int tid = threadIdx.x;
    const int lane = tid & 31, wid = tid >> 5;
    const int wm = wid & 3, wn = wid >> 2;  // 4 x 4 warp grid
    const float* Ab = A + (size_t)blockIdx.z * aB;
    const float* Bb = Bm + (size_t)blockIdx.z * bB;
    const int m0 = blockIdx.y * 128;
    const int n0 = blockIdx.x * 128;

    float acc[2][4][4];
#pragma unroll
    for (int i = 0; i < 2; ++i)
#pragma unroll
        for (int j = 0; j < 4; ++j)
#pragma unroll
            for (int e = 0; e < 4; ++e) acc[i][j][e] = 0.f;

    float4 ra[2], rb[2];
    auto ldg = [&](int kt) {
#pragma unroll
        for (int it = 0; it < 2; ++it) {
            int idx = tid + (it << 9);
            if (A_KM) {
                int kk = idx >> 5, m4 = idx & 31;
                ra[it] = *reinterpret_cast<const float4*>(
                    Ab + (size_t)(kt * 32 + kk) * lda + m0 + (m4 << 2));
            } else {
                int mm = idx >> 3, k4 = idx & 7;
                ra[it] = *reinterpret_cast<const float4*>(
                    Ab + (size_t)(m0 + mm) * lda + kt * 32 + (k4 << 2));
            }
            if (B_KN) {
                int kk = idx >> 5, n4 = idx & 31;
                rb[it] = *reinterpret_cast<const float4*>(
                    Bb + (size_t)(kt * 32 + kk) * ldb + n0 + (n4 << 2));
            } else {
                int nn = idx >> 3, k4 = idx & 7;
                rb[it] = *reinterpret_cast<const float4*>(
                    Bb + (size_t)(n0 + nn) * ldb + kt * 32 + (k4 << 2));
            }
        }
    };
    auto sts = [&](int buf) {
        float* Ad = sm + buf * ASTG;
        float* Bd = sm + BOFF + buf * BSTG;
#pragma unroll
        for (int it = 0; it < 2; ++it) {
            int idx = tid + (it << 9);
            float va[4] = {ra[it].x, ra[it].y, ra[it].z, ra[it].w};
            float vb[4] = {rb[it].x, rb[it].y, rb[it].z, rb[it].w};
            if (A_KM) {
                int kk = idx >> 5, m4 = idx & 31;
                int s = kk >> 3, kh = (kk & 7) >> 2, kq = kk & 3;
#pragma unroll
                for (int c = 0; c < 4; ++c) {
                    int m = (m4 << 2) + c;
                    Ad[s * 1060 + (m >> 4) * 132 + (((m & 7) << 2) + kq) * 4 +
                       ((m >> 3) & 1) + (kh << 1)] = va[c];
                }
            } else {
                int mm = idx >> 3, k4 = idx & 7;
                int s = k4 >> 1, kh = k4 & 1;
                int mt = mm >> 4, reg = ((mm >> 3) & 1) + (kh << 1);
#pragma unroll
                for (int c = 0; c < 4; ++c)
                    Ad[s * 1060 + mt * 132 + (((mm & 7) << 2) + c) * 4 + reg] =
                        va[c];
            }
            if (B_KN) {
                int kk = idx >> 5, n4 = idx & 31;
                int s = kk >> 3, kh = (kk & 7) >> 2, kq = kk & 3;
#pragma unroll
                for (int c = 0; c < 4; ++c) {
                    int n = (n4 << 2) + c;
                    Bd[s * 1058 + (n >> 3) * 66 + (((n & 7) << 2) + kq) * 2 +
                       kh] = vb[c];
                }
            } else {
                int nn = idx >> 3, k4 = idx & 7;
                int s = k4 >> 1, kh = k4 & 1, nt = nn >> 3;
#pragma unroll
                for (int c = 0; c < 4; ++c)
                    Bd[s * 1058 + nt * 66 + (((nn & 7) << 2) + c) * 2 + kh] =
                        vb[c];
            }
        }
    };
    auto compute = [&](int buf) {
        const float* Ad = sm + buf * ASTG;
        const float* Bd = sm + BOFF + buf * BSTG;
#pragma unroll
        for (int s = 0; s < 4; ++s) {
            uint32_t ah[2][4], al[2][4], bh[4][2], bl[4][2];
#pragma unroll
            for (int i = 0; i < 2; ++i) {
                float4 a = *reinterpret_cast<const float4*>(
                    Ad + s * 1060 + ((wm << 1) + i) * 132 + (lane << 2));
                float av[4] = {a.x, a.y, a.z, a.w};
#pragma unroll
                for (int e = 0; e < 4; ++e) {
                    uint32_t h = tf32_hi(av[e]);
                    ah[i][e] = h;
                    al[i][e] = __float_as_uint(av[e] - __uint_as_float(h));
                }
            }
#pragma unroll
            for (int j = 0; j < 4; ++j) {
                float2 b = *reinterpret_cast<const float2*>(
                    Bd + s * 1058 + ((wn << 2) + j) * 66 + (lane << 1));
                float bv[2] = {b.x, b.y};
#pragma unroll
                for (int e = 0; e < 2; ++e) {
                    uint32_t h = tf32_hi(bv[e]);
                    bh[j][e] = h;
                    bl[j][e] = __float_as_uint(bv[e] - __uint_as_float(h));
                }
            }
#pragma unroll
            for (int i = 0; i < 2; ++i)
#pragma unroll
                for (int j = 0; j < 4; ++j) {
                    mma8(acc[i][j], ah[i], bh[j]);
                    mma8(acc[i][j], ah[i], bl[j]);
                    mma8(acc[i][j], al[i], bh[j]);
                }
        }
    };

    ldg(0);
    sts(0);
    __syncthreads();
    const int nt = K >> 5;
    for (int t = 0; t < nt; ++t) {
        if (t + 1 < nt) ldg(t + 1);
        compute(t & 1);
        if (t + 1 < nt) sts((t + 1) & 1);  // other buffer: no conflict
        __syncthreads();
    }

    const int r = lane >> 2, cq = (lane & 3) << 1;
    float* Cb = C + (size_t)blockIdx.z * cB;
#pragma unroll
    for (int i = 0; i < 2; ++i) {
#pragma unroll
        for (int j = 0; j < 4; ++j) {
            const int row = m0 + (wm << 5) + (i << 4) + r;
            const int col = n0 + (wn << 5) + (j << 3) + cq;
            float o0 = acc[i][j][0], o1 = acc[i][j][1];
            float o2 = acc[i][j][2], o3 = acc[i][j][3];
            if (HAS_BIAS) {
                float b0 = bias[col], b1 = bias[col + 1];
                o0 += b0; o1 += b1; o2 += b0; o3 += b1;
            }
            *reinterpret_cast<float2*>(Cb + (size_t)row * Nn + col) =
                make_float2(o0, o1);
            *reinterpret_cast<float2*>(Cb + (size_t)(row + 8) * Nn + col) =
                make_float2(o2, o3);
        }
    }
}

// ---------------------------------------------------------------------------
// s[b][e] = sum_n x[b][n][e]
// ---------------------------------------------------------------------------
__global__ void __launch_bounds__(256)
colsum_kernel(const float* __restrict__ x, float* __restrict__ s) {
    const int e = blockIdx.x * 256 + threadIdx.x;
    const int b = blockIdx.y;
    const float* p = x + (size_t)b * N_ * D_ + e;
    float a0 = 0.f, a1 = 0.f, a2 = 0.f, a3 = 0.f;
    for (int n = 0; n < N_; n += 4) {
        a0 += p[(size_t)n * D_];
        a1 += p[(size_t)(n + 1) * D_];
        a2 += p[(size_t)(n + 2) * D_];
        a3 += p[(size_t)(n + 3) * D_];
    }
    s[b * D_ + e] = (a0 + a1) + (a2 + a3);
}

// u[b][e] = Wq[e].s[b] ;  w'[b][f] = Wk[f].s[b] + N*bk[f]
__global__ void __launch_bounds__(256)
gemv_kernel(const float* __restrict__ Wq, const float* __restrict__ Wk,
            const float* __restrict__ bk, const float* __restrict__ s,
            float* __restrict__ u, float* __restrict__ w) {
    const int wg = blockIdx.x * 8 + (threadIdx.x >> 5);
    const int lane = threadIdx.x & 31;
    const int b = wg >> 11;           // 2048 outputs per batch
    const int o = wg & 2047;
    const bool is_u = o < 1024;
    const int row = is_u ? o : o - 1024;
    const float* W = (is_u ? Wq : Wk) + (size_t)row * D_;
    const float* sb = s + b * D_;
    float acc = 0.f;
#pragma unroll
    for (int i = 0; i < 32; ++i) acc += W[lane + (i << 5)] * sb[lane + (i << 5)];
#pragma unroll
    for (int off = 16; off; off >>= 1)
        acc += __shfl_xor_sync(0xffffffffu, acc, off);
    if (lane == 0) {
        if (is_u) u[b * D_ + row] = acc;
        else      w[b * D_ + row] = acc + (float)N_ * bk[row];
    }
}

// ---------------------------------------------------------------------------
// softmax with fused rank-1 corrections:
// logit[b][e][f] = L + u[b][e]*bk[f] + bq[e]*w'[b][f]; softmax over f, inplace
// ---------------------------------------------------------------------------
__global__ void __launch_bounds__(256)
softmax_fused(float* __restrict__ L, const float* __restrict__ u,
              const float* __restrict__ w, const float* __restrict__ bq,
              const float* __restrict__ bk) {
    const int row = blockIdx.x;
    const int b = row >> 10, e = row & 1023;
    float* p = L + (size_t)row * 1024;
    const float uu = u[b * D_ + e];
    const float bb = bq[e];
    const float* wb = w + b * D_;
    const int t = threadIdx.x;
    const int lane = t & 31, wid = t >> 5;
    __shared__ float red[8];

    float v[4];
#pragma unroll
    for (int i = 0; i < 4; ++i) {
        const int f = t + (i << 8);
        v[i] = p[f] + uu * bk[f] + bb * wb[f];
    }

    float m = fmaxf(fmaxf(v[0], v[1]), fmaxf(v[2], v[3]));
#pragma unroll
    for (int o = 16; o; o >>= 1) m = fmaxf(m, __shfl_xor_sync(0xffffffffu, m, o));
    if (lane == 0) red[wid] = m;
    __syncthreads();
    if (t < 32) {
        float x = (t < 8) ? red[t] : -3.4e38f;
#pragma unroll
        for (int o = 4; o; o >>= 1) x = fmaxf(x, __shfl_xor_sync(0xffffffffu, x, o));
        if (t == 0) red[0] = x;
    }
    __syncthreads();
    m = red[0];
    __syncthreads();

    float ssum = 0.f;
#pragma unroll
    for (int i = 0; i < 4; ++i) {
        v[i] = expf(v[i] - m);
        ssum += v[i];
    }
#pragma unroll
    for (int o = 16; o; o >>= 1) ssum += __shfl_xor_sync(0xffffffffu, ssum, o);
    if (lane == 0) red[wid] = ssum;
    __syncthreads();
    if (t < 32) {
        float x = (t < 8) ? red[t] : 0.f;
#pragma unroll
        for (int o = 4; o; o >>= 1) x += __shfl_xor_sync(0xffffffffu, x, o);
        if (t == 0) red[0] = x;
    }
    __syncthreads();
    const float inv = 1.0f / red[0];
#pragma unroll
    for (int i = 0; i < 4; ++i) p[t + (i << 8)] = v[i] * inv;
}

extern "C" void kernel_launch(void* const* d_in, const int* in_sizes, int n_in,
                              void* d_out, int out_size) {
    const float* x  = (const float*)d_in[0];
    const float* Wq = (const float*)d_in[1];
    const float* bq = (const float*)d_in[2];
    const float* Wk = (const float*)d_in[3];
    const float* bk = (const float*)d_in[4];
    const float* Wv = (const float*)d_in[5];
    const float* bv = (const float*)d_in[6];
    float* out = (float*)d_out;

    float *v, *G, *T1, *L, *s, *u, *w;
    cudaGetSymbolAddress((void**)&v, g_v);
    cudaGetSymbolAddress((void**)&G, g_G);
    cudaGetSymbolAddress((void**)&T1, g_T1);
    cudaGetSymbolAddress((void**)&L, g_L);
    cudaGetSymbolAddress((void**)&s, g_s);
    cudaGetSymbolAddress((void**)&u, g_u);
    cudaGetSymbolAddress((void**)&w, g_w);

    cudaFuncSetAttribute(mma_gemm<false, false, true>,
                         cudaFuncAttributeMaxDynamicSharedMemorySize, SMEM_BYTES);
    cudaFuncSetAttribute(mma_gemm<true, true, false>,
                         cudaFuncAttributeMaxDynamicSharedMemorySize, SMEM_BYTES);
    cudaFuncSetAttribute(mma_gemm<false, false, false>,
                         cudaFuncAttributeMaxDynamicSharedMemorySize, SMEM_BYTES);
    cudaFuncSetAttribute(mma_gemm<false, true, false>,
                         cudaFuncAttributeMaxDynamicSharedMemorySize, SMEM_BYTES);

    const dim3 blk(512);

    // v = x @ Wv^T + bv      [32768,1024] x [1024,1024]
    mma_gemm<false, false, true><<<dim3(8, 256, 1), blk, SMEM_BYTES>>>(
        x, Wv, bv, v, B_ * N_, D_, D_, D_, D_, 0, 0, 0);

    // s = x^T 1 ; u = Wq s ; w' = Wk s + N bk
    colsum_kernel<<<dim3(4, 8), 256>>>(x, s);
    gemv_kernel<<<2048, 256>>>(Wq, Wk, bk, s, u, w);

    // G[b] = x[b]^T x[b]     M=N=1024, K=4096
    mma_gemm<true, true, false><<<dim3(8, 8, B_), blk, SMEM_BYTES>>>(
        x, x, nullptr, G, D_, D_, N_, D_, D_,
        (size_t)N_ * D_, (size_t)N_ * D_, (size_t)D_ * D_);

    // T1[b] = G[b] @ Wk^T    M=N=K=1024
    mma_gemm<false, false, false><<<dim3(8, 8, B_), blk, SMEM_BYTES>>>(
        G, Wk, nullptr, T1, D_, D_, D_, D_, D_,
        (size_t)D_ * D_, 0, (size_t)D_ * D_);

    // L[b] = Wq @ T1[b]      M=N=K=1024
    mma_gemm<false, true, false><<<dim3(8, 8, B_), blk, SMEM_BYTES>>>(
        Wq, T1, nullptr, L, D_, D_, D_, D_, D_,
        0, (size_t)D_ * D_, (size_t)D_ * D_);

    // softmax with rank-1 corrections, in place -> attn
    softmax_fused<<<B_ * D_, 256>>>(L, u, w, bq, bk);

    // out[b] = v[b] @ attn[b]   M=4096, N=1024, K=1024
    mma_gemm<false, true, false><<<dim3(8, 32, B_), blk, SMEM_BYTES>>>(
        v, L, nullptr, out, N_, D_, D_, D_, D_,
        (size_t)N_ * D_, (size_t)D_ * D_, (size_t)N_ * D_);
}

// round 6
// speedup vs baseline: 1.8538x; 1.0896x over previous
#include <cuda_runtime.h>
#include <cstdint>

#define B_   8
#define N_   4096
#define D_   1024

// scratch (device globals; no allocations allowed)
__device__ float g_v [(size_t)B_ * N_ * D_];   // v projection      128 MB
__device__ float g_G [(size_t)B_ * D_ * D_];   // G = x^T x          32 MB
__device__ float g_T1[(size_t)B_ * D_ * D_];   // T1 = G Wk^T        32 MB
__device__ float g_L [(size_t)B_ * D_ * D_];   // logits -> attn     32 MB
__device__ float g_s [(size_t)B_ * D_];        // s = x^T 1
__device__ float g_u [(size_t)B_ * D_];        // u = Wq s
__device__ float g_w [(size_t)B_ * D_];        // w' = Wk s + N*bk

__device__ __forceinline__ uint32_t tf32_hi(float x) {
    uint32_t r;
    asm("cvt.rna.tf32.f32 %0, %1;" : "=r"(r) : "f"(x));
    return r;
}
__device__ __forceinline__ void mma8(float* c, const uint32_t* a,
                                     const uint32_t* b) {
    asm("mma.sync.aligned.m16n8k8.row.col.f32.tf32.tf32.f32 "
        "{%0,%1,%2,%3}, {%4,%5,%6,%7}, {%8,%9}, {%0,%1,%2,%3};"
        : "+f"(c[0]), "+f"(c[1]), "+f"(c[2]), "+f"(c[3])
        : "r"(a[0]), "r"(a[1]), "r"(a[2]), "r"(a[3]), "r"(b[0]), "r"(b[1]));
}

// ---------------------------------------------------------------------------
// TF32 (3x split) mma.sync GEMM: C[M,N] = A * B^T  (K-contracted) (+bias)
//   A_KM=false: A stored [M,K] (k contig), true: [K,M] (m contig)
//   B_KN=false: B stored [N,K] (k contig), true: [K,N] (n contig)
// CTA 128x128, 512 threads, warp grid 4x4, warp tile 32x32, K-stage 32,
// double-buffered. hi/lo tf32 split done ONCE at store time into parallel
// SMEM copies -> mainloop is pure LDS + MMA (no cvt/sub on the issue path).
// Fragment layout (padded, conflict-free):
//   A: idx = s*1060 + mt*132 + lane*4 + reg   (s<4, mt<8, reg<4)
//   B: idx = s*1058 + nt*66  + lane*2 + reg   (nt<16, reg<2)
// Regions: Ahi[2 buf] | Alo[2 buf] | Bhi[2 buf] | Blo[2 buf]
// ---------------------------------------------------------------------------
constexpr int ASTG = 4240, BSTG = 4232;
constexpr int AHI0 = 0;
constexpr int ALO0 = 2 * ASTG;
constexpr int BHI0 = 4 * ASTG;
constexpr int BLO0 = 4 * ASTG + 2 * BSTG;
constexpr int SMEM_BYTES = (4 * ASTG + 4 * BSTG) * 4;  // 135,552 B

template <bool A_KM, bool B_KN, bool HAS_BIAS>
__global__ void __launch_bounds__(512, 1)
mma_gemm(const float* __restrict__ A, const float* __restrict__ Bm,
         const float* __restrict__ bias, float* __restrict__ C,
         int M, int Nn, int K, int lda, int ldb,
         size_t aB, size_t bB, size_t cB) {
    extern __shared__ float sm[];
    uint32_t* smu = reinterpret_cast<uint32_t*>(sm);
    const int tid = threadIdx.x;
    const int lane = tid & 31, wid = tid >> 5;
    const int wm = wid & 3, wn = wid >> 2;  // 4 x 4 warp grid
    const float* Ab = A + (size_t)blockIdx.z * aB;
    const float* Bb = Bm + (size_t)blockIdx.z * bB;
    const int m0 = blockIdx.y * 128;
    const int n0 = blockIdx.x * 128;

    float acc[2][4][4];
#pragma unroll
    for (int i = 0; i < 2; ++i)
#pragma unroll
        for (int j = 0; j < 4; ++j)
#pragma unroll
            for (int e = 0; e < 4; ++e) acc[i][j][e] = 0.f;

    float4 ra[2], rb[2];
    auto ldg = [&](int kt) {
#pragma unroll
        for (int it = 0; it < 2; ++it) {
            int idx = tid + (it << 9);
            if (A_KM) {
                int kk = idx >> 5, m4 = idx & 31;
                ra[it] = *reinterpret_cast<const float4*>(
                    Ab + (size_t)(kt * 32 + kk) * lda + m0 + (m4 << 2));
            } else {
                int mm = idx >> 3, k4 = idx & 7;
                ra[it] = *reinterpret_cast<const float4*>(
                    Ab + (size_t)(m0 + mm) * lda + kt * 32 + (k4 << 2));
            }
            if (B_KN) {
                int kk = idx >> 5, n4 = idx & 31;
                rb[it] = *reinterpret_cast<const float4*>(
                    Bb + (size_t)(kt * 32 + kk) * ldb + n0 + (n4 << 2));
            } else {
                int nn = idx >> 3, k4 = idx & 7;
                rb[it] = *reinterpret_cast<const float4*>(
                    Bb + (size_t)(n0 + nn) * ldb + kt * 32 + (k4 << 2));
            }
        }
    };
    auto sts = [&](int buf) {
        uint32_t* Ah = smu + AHI0 + buf * ASTG;
        uint32_t* Al = smu + ALO0 + buf * ASTG;
        uint32_t* Bh = smu + BHI0 + buf * BSTG;
        uint32_t* Bl = smu + BLO0 + buf * BSTG;
#pragma unroll
        for (int it = 0; it < 2; ++it) {
            int idx = tid + (it << 9);
            float va[4] = {ra[it].x, ra[it].y, ra[it].z, ra[it].w};
            float vb[4] = {rb[it].x, rb[it].y, rb[it].z, rb[it].w};
            uint32_t hA[4], lA[4], hB[4], lB[4];
#pragma unroll
            for (int c = 0; c < 4; ++c) {
                hA[c] = tf32_hi(va[c]);
                lA[c] = __float_as_uint(va[c] - __uint_as_float(hA[c]));
                hB[c] = tf32_hi(vb[c]);
                lB[c] = __float_as_uint(vb[c] - __uint_as_float(hB[c]));
            }
            if (A_KM) {
                int kk = idx >> 5, m4 = idx & 31;
                int s = kk >> 3, kh = (kk & 7) >> 2, kq = kk & 3;
#pragma unroll
                for (int c = 0; c < 4; ++c) {
                    int m = (m4 << 2) + c;
                    int o = s * 1060 + (m >> 4) * 132 +
                            (((m & 7) << 2) + kq) * 4 + ((m >> 3) & 1) +
                            (kh << 1);
                    Ah[o] = hA[c];
                    Al[o] = lA[c];
                }
            } else {
                int mm = idx >> 3, k4 = idx & 7;
                int s = k4 >> 1, kh = k4 & 1;
                int mt = mm >> 4, reg = ((mm >> 3) & 1) + (kh << 1);
#pragma unroll
                for (int c = 0; c < 4; ++c) {
                    int o = s * 1060 + mt * 132 + (((mm & 7) << 2) + c) * 4 + reg;
                    Ah[o] = hA[c];
                    Al[o] = lA[c];
                }
            }
            if (B_KN) {
                int kk = idx >> 5, n4 = idx & 31;
                int s = kk >> 3, kh = (kk & 7) >> 2, kq = kk & 3;
#pragma unroll
                for (int c = 0; c < 4; ++c) {
                    int n = (n4 << 2) + c;
                    int o = s * 1058 + (n >> 3) * 66 +
                            (((n & 7) << 2) + kq) * 2 + kh;
                    Bh[o] = hB[c];
                    Bl[o] = lB[c];
                }
            } else {
                int nn = idx >> 3, k4 = idx & 7;
                int s = k4 >> 1, kh = k4 & 1, nt = nn >> 3;
#pragma unroll
                for (int c = 0; c < 4; ++c) {
                    int o = s * 1058 + nt * 66 + (((nn & 7) << 2) + c) * 2 + kh;
                    Bh[o] = hB[c];
                    Bl[o] = lB[c];
                }
            }
        }
    };
    auto compute = [&](int buf) {
        const uint32_t* Ah = smu + AHI0 + buf * ASTG;
        const uint32_t* Al = smu + ALO0 + buf * ASTG;
        const uint32_t* Bh = smu + BHI0 + buf * BSTG;
        const uint32_t* Bl = smu + BLO0 + buf * BSTG;
#pragma unroll
        for (int s = 0; s < 4; ++s) {
            uint32_t ah[2][4], al[2][4], bh[4][2], bl[4][2];
#pragma unroll
            for (int i = 0; i < 2; ++i) {
                const int o = s * 1060 + ((wm << 1) + i) * 132 + (lane << 2);
                *reinterpret_cast<uint4*>(ah[i]) =
                    *reinterpret_cast<const uint4*>(Ah + o);
                *reinterpret_cast<uint4*>(al[i]) =
                    *reinterpret_cast<const uint4*>(Al + o);
            }
#pragma unroll
            for (int j = 0; j < 4; ++j) {
                const int o = s * 1058 + ((wn << 2) + j) * 66 + (lane << 1);
                *reinterpret_cast<uint2*>(bh[j]) =
                    *reinterpret_cast<const uint2*>(Bh + o);
                *reinterpret_cast<uint2*>(bl[j]) =
                    *reinterpret_cast<const uint2*>(Bl + o);
            }
#pragma unroll
            for (int i = 0; i < 2; ++i)
#pragma unroll
                for (int j = 0; j < 4; ++j) {
                    mma8(acc[i][j], ah[i], bh[j]);
                    mma8(acc[i][j], ah[i], bl[j]);
                    mma8(acc[i][j], al[i], bh[j]);
                }
        }
    };

    ldg(0);
    sts(0);
    __syncthreads();
    const int nt = K >> 5;
    for (int t = 0; t < nt; ++t) {
        if (t + 1 < nt) ldg(t + 1);
        compute(t & 1);
        if (t + 1 < nt) sts((t + 1) & 1);  // other buffer: no conflict
        __syncthreads();
    }

    const int r = lane >> 2, cq = (lane & 3) << 1;
    float* Cb = C + (size_t)blockIdx.z * cB;
#pragma unroll
    for (int i = 0; i < 2; ++i) {
#pragma unroll
        for (int j = 0; j < 4; ++j) {
            const int row = m0 + (wm << 5) + (i << 4) + r;
            const int col = n0 + (wn << 5) + (j << 3) + cq;
            float o0 = acc[i][j][0], o1 = acc[i][j][1];
            float o2 = acc[i][j][2], o3 = acc[i][j][3];
            if (HAS_BIAS) {
                float b0 = bias[col], b1 = bias[col + 1];
                o0 += b0; o1 += b1; o2 += b0; o3 += b1;
            }
            *reinterpret_cast<float2*>(Cb + (size_t)row * Nn + col) =
                make_float2(o0, o1);
            *reinterpret_cast<float2*>(Cb + (size_t)(row + 8) * Nn + col) =
                make_float2(o2, o3);
        }
    }
}

// ---------------------------------------------------------------------------
// s[b][e] = sum_n x[b][n][e]
// ---------------------------------------------------------------------------
__global__ void __launch_bounds__(256)
colsum_kernel(const float* __restrict__ x, float* __restrict__ s) {
    const int e = blockIdx.x * 256 + threadIdx.x;
    const int b = blockIdx.y;
    const float* p = x + (size_t)b * N_ * D_ + e;
    float a0 = 0.f, a1 = 0.f, a2 = 0.f, a3 = 0.f;
    for (int n = 0; n < N_; n += 4) {
        a0 += p[(size_t)n * D_];
        a1 += p[(size_t)(n + 1) * D_];
        a2 += p[(size_t)(n + 2) * D_];
        a3 += p[(size_t)(n + 3) * D_];
    }
    s[b * D_ + e] = (a0 + a1) + (a2 + a3);
}

// u[b][e] = Wq[e].s[b] ;  w'[b][f] = Wk[f].s[b] + N*bk[f]
__global__ void __launch_bounds__(256)
gemv_kernel(const float* __restrict__ Wq, const float* __restrict__ Wk,
            const float* __restrict__ bk, const float* __restrict__ s,
            float* __restrict__ u, float* __restrict__ w) {
    const int wg = blockIdx.x * 8 + (threadIdx.x >> 5);
    const int lane = threadIdx.x & 31;
    const int b = wg >> 11;           // 2048 outputs per batch
    const int o = wg & 2047;
    const bool is_u = o < 1024;
    const int row = is_u ? o : o - 1024;
    const float* W = (is_u ? Wq : Wk) + (size_t)row * D_;
    const float* sb = s + b * D_;
    float acc = 0.f;
#pragma unroll
    for (int i = 0; i < 32; ++i) acc += W[lane + (i << 5)] * sb[lane + (i << 5)];
#pragma unroll
    for (int off = 16; off; off >>= 1)
        acc += __shfl_xor_sync(0xffffffffu, acc, off);
    if (lane == 0) {
        if (is_u) u[b * D_ + row] = acc;
        else      w[b * D_ + row] = acc + (float)N_ * bk[row];
    }
}

// ---------------------------------------------------------------------------
// softmax with fused rank-1 corrections:
// logit[b][e][f] = L + u[b][e]*bk[f] + bq[e]*w'[b][f]; softmax over f, inplace
// ---------------------------------------------------------------------------
__global__ void __launch_bounds__(256)
softmax_fused(float* __restrict__ L, const float* __restrict__ u,
              const float* __restrict__ w, const float* __restrict__ bq,
              const float* __restrict__ bk) {
    const int row = blockIdx.x;
    const int b = row >> 10, e = row & 1023;
    float* p = L + (size_t)row * 1024;
    const float uu = u[b * D_ + e];
    const float bb = bq[e];
    const float* wb = w + b * D_;
    const int t = threadIdx.x;
    const int lane = t & 31, wid = t >> 5;
    __shared__ float red[8];

    float v[4];
#pragma unroll
    for (int i = 0; i < 4; ++i) {
        const int f = t + (i << 8);
        v[i] = p[f] + uu * bk[f] + bb * wb[f];
    }

    float m = fmaxf(fmaxf(v[0], v[1]), fmaxf(v[2], v[3]));
#pragma unroll
    for (int o = 16; o; o >>= 1) m = fmaxf(m, __shfl_xor_sync(0xffffffffu, m, o));
    if (lane == 0) red[wid] = m;
    __syncthreads();
    if (t < 32) {
        float x = (t < 8) ? red[t] : -3.4e38f;
#pragma unroll
        for (int o = 4; o; o >>= 1) x = fmaxf(x, __shfl_xor_sync(0xffffffffu, x, o));
        if (t == 0) red[0] = x;
    }
    __syncthreads();
    m = red[0];
    __syncthreads();

    float ssum = 0.f;
#pragma unroll
    for (int i = 0; i < 4; ++i) {
        v[i] = expf(v[i] - m);
        ssum += v[i];
    }
#pragma unroll
    for (int o = 16; o; o >>= 1) ssum += __shfl_xor_sync(0xffffffffu, ssum, o);
    if (lane == 0) red[wid] = ssum;
    __syncthreads();
    if (t < 32) {
        float x = (t < 8) ? red[t] : 0.f;
#pragma unroll
        for (int o = 4; o; o >>= 1) x += __shfl_xor_sync(0xffffffffu, x, o);
        if (t == 0) red[0] = x;
    }
    __syncthreads();
    const float inv = 1.0f / red[0];
#pragma unroll
    for (int i = 0; i < 4; ++i) p[t + (i << 8)] = v[i] * inv;
}

extern "C" void kernel_launch(void* const* d_in, const int* in_sizes, int n_in,
                              void* d_out, int out_size) {
    const float* x  = (const float*)d_in[0];
    const float* Wq = (const float*)d_in[1];
    const float* bq = (const float*)d_in[2];
    const float* Wk = (const float*)d_in[3];
    const float* bk = (const float*)d_in[4];
    const float* Wv = (const float*)d_in[5];
    const float* bv = (const float*)d_in[6];
    float* out = (float*)d_out;

    float *v, *G, *T1, *L, *s, *u, *w;
    cudaGetSymbolAddress((void**)&v, g_v);
    cudaGetSymbolAddress((void**)&G, g_G);
    cudaGetSymbolAddress((void**)&T1, g_T1);
    cudaGetSymbolAddress((void**)&L, g_L);
    cudaGetSymbolAddress((void**)&s, g_s);
    cudaGetSymbolAddress((void**)&u, g_u);
    cudaGetSymbolAddress((void**)&w, g_w);

    cudaFuncSetAttribute(mma_gemm<false, false, true>,
                         cudaFuncAttributeMaxDynamicSharedMemorySize, SMEM_BYTES);
    cudaFuncSetAttribute(mma_gemm<true, true, false>,
                         cudaFuncAttributeMaxDynamicSharedMemorySize, SMEM_BYTES);
    cudaFuncSetAttribute(mma_gemm<false, false, false>,
                         cudaFuncAttributeMaxDynamicSharedMemorySize, SMEM_BYTES);
    cudaFuncSetAttribute(mma_gemm<false, true, false>,
                         cudaFuncAttributeMaxDynamicSharedMemorySize, SMEM_BYTES);

    const dim3 blk(512);

    // v = x @ Wv^T + bv      [32768,1024] x [1024,1024]
    mma_gemm<false, false, true><<<dim3(8, 256, 1), blk, SMEM_BYTES>>>(
        x, Wv, bv, v, B_ * N_, D_, D_, D_, D_, 0, 0, 0);

    // s = x^T 1 ; u = Wq s ; w' = Wk s + N bk
    colsum_kernel<<<dim3(4, 8), 256>>>(x, s);
    gemv_kernel<<<2048, 256>>>(Wq, Wk, bk, s, u, w);

    // G[b] = x[b]^T x[b]     M=N=1024, K=4096
    mma_gemm<true, true, false><<<dim3(8, 8, B_), blk, SMEM_BYTES>>>(
        x, x, nullptr, G, D_, D_, N_, D_, D_,
        (size_t)N_ * D_, (size_t)N_ * D_, (size_t)D_ * D_);

    // T1[b] = G[b] @ Wk^T    M=N=K=1024
    mma_gemm<false, false, false><<<dim3(8, 8, B_), blk, SMEM_BYTES>>>(
        G, Wk, nullptr, T1, D_, D_, D_, D_, D_,
        (size_t)D_ * D_, 0, (size_t)D_ * D_);

    // L[b] = Wq @ T1[b]      M=N=K=1024
    mma_gemm<false, true, false><<<dim3(8, 8, B_), blk, SMEM_BYTES>>>(
        Wq, T1, nullptr, L, D_, D_, D_, D_, D_,
        0, (size_t)D_ * D_, (size_t)D_ * D_);

    // softmax with rank-1 corrections, in place -> attn
    softmax_fused<<<B_ * D_, 256>>>(L, u, w, bq, bk);

    // out[b] = v[b] @ attn[b]   M=4096, N=1024, K=1024
    mma_gemm<false, true, false><<<dim3(8, 32, B_), blk, SMEM_BYTES>>>(
        v, L, nullptr, out, N_, D_, D_, D_, D_,
        (size_t)N_ * D_, (size_t)D_ * D_, (size_t)N_ * D_);
}

// round 7
// speedup vs baseline: 1.8659x; 1.0065x over previous
#include <cuda_runtime.h>
#include <cstdint>

#define B_   8
#define N_   4096
#define D_   1024

// scratch (device globals; no allocations allowed)
__device__ float g_v [(size_t)B_ * N_ * D_];   // v projection      128 MB
__device__ float g_G [(size_t)B_ * D_ * D_];   // G = x^T x          32 MB
__device__ float g_T1[(size_t)B_ * D_ * D_];   // T1 = G Wk^T        32 MB
__device__ float g_L [(size_t)B_ * D_ * D_];   // logits -> attn     32 MB
__device__ float g_s [(size_t)B_ * D_];        // s = x^T 1
__device__ float g_u [(size_t)B_ * D_];        // u = Wq s
__device__ float g_w [(size_t)B_ * D_];        // w' = Wk s + N*bk

__device__ __forceinline__ uint32_t tf32_hi(float x) {
    uint32_t r;
    asm("cvt.rna.tf32.f32 %0, %1;" : "=r"(r) : "f"(x));
    return r;
}
__device__ __forceinline__ void mma8(float* c, const uint32_t* a,
                                     const uint32_t* b) {
    asm("mma.sync.aligned.m16n8k8.row.col.f32.tf32.tf32.f32 "
        "{%0,%1,%2,%3}, {%4,%5,%6,%7}, {%8,%9}, {%0,%1,%2,%3};"
        : "+f"(c[0]), "+f"(c[1]), "+f"(c[2]), "+f"(c[3])
        : "r"(a[0]), "r"(a[1]), "r"(a[2]), "r"(a[3]), "r"(b[0]), "r"(b[1]));
}

// ---------------------------------------------------------------------------
// TF32 (3x split) mma.sync GEMM: C[M,N] = A * B^T  (K-contracted) (+bias)
//   A_KM=false: A stored [M,K] (k contig), true: [K,M] (m contig)
//   B_KN=false: B stored [N,K] (k contig), true: [K,N] (n contig)
// CTA 128x128, 256 threads, 8 warps (grid 2x4), warp tile 64x32.
// K-stage 16, double-buffered; hi/lo tf32 split done once at store time.
// 2 CTAs per SM (launch_bounds) so sts/sync tails of one CTA overlap the
// other CTA's MMA stream.
// Fragment layout (padded, conflict-free), s<2 k-steps per stage:
//   A: idx = s*1060 + mt*132 + lane*4 + reg   (mt<8, reg<4)
//   B: idx = s*1058 + nt*66  + lane*2 + reg   (nt<16, reg<2)
// Regions: Ahi[2 buf] | Alo[2 buf] | Bhi[2 buf] | Blo[2 buf]
// ---------------------------------------------------------------------------
constexpr int ASTG = 2120, BSTG = 2116;
constexpr int AHI0 = 0;
constexpr int ALO0 = 2 * ASTG;
constexpr int BHI0 = 4 * ASTG;
constexpr int BLO0 = 4 * ASTG + 2 * BSTG;
constexpr int SMEM_BYTES = (4 * ASTG + 4 * BSTG) * 4;  // 67,776 B

template <bool A_KM, bool B_KN, bool HAS_BIAS>
__global__ void __launch_bounds__(256, 2)
mma_gemm(const float* __restrict__ A, const float* __restrict__ Bm,
         const float* __restrict__ bias, float* __restrict__ C,
         int M, int Nn, int K, int lda, int ldb,
         size_t aB, size_t bB, size_t cB) {
    extern __shared__ float sm[];
    uint32_t* smu = reinterpret_cast<uint32_t*>(sm);
    const int tid = threadIdx.x;
    const int lane = tid & 31, wid = tid >> 5;
    const int wm = wid & 1, wn = wid >> 1;  // warp grid 2(M) x 4(N)
    const float* Ab = A + (size_t)blockIdx.z * aB;
    const float* Bb = Bm + (size_t)blockIdx.z * bB;
    const int m0 = blockIdx.y * 128;
    const int n0 = blockIdx.x * 128;

    float acc[4][4][4];
#pragma unroll
    for (int i = 0; i < 4; ++i)
#pragma unroll
        for (int j = 0; j < 4; ++j)
#pragma unroll
            for (int e = 0; e < 4; ++e) acc[i][j][e] = 0.f;

    // per stage: A tile 128x16 = 512 float4, B tile 128x16 = 512 float4
    // 256 threads -> 2 chunks each per operand
    float4 ra[2], rb[2];
    auto ldg = [&](int kt) {
#pragma unroll
        for (int it = 0; it < 2; ++it) {
            int idx = tid + (it << 8);
            if (A_KM) {
                int kk = idx >> 5, m4 = idx & 31;
                ra[it] = *reinterpret_cast<const float4*>(
                    Ab + (size_t)(kt * 16 + kk) * lda + m0 + (m4 << 2));
            } else {
                int mm = idx >> 2, k4 = idx & 3;
                ra[it] = *reinterpret_cast<const float4*>(
                    Ab + (size_t)(m0 + mm) * lda + kt * 16 + (k4 << 2));
            }
            if (B_KN) {
                int kk = idx >> 5, n4 = idx & 31;
                rb[it] = *reinterpret_cast<const float4*>(
                    Bb + (size_t)(kt * 16 + kk) * ldb + n0 + (n4 << 2));
            } else {
                int nn = idx >> 2, k4 = idx & 3;
                rb[it] = *reinterpret_cast<const float4*>(
                    Bb + (size_t)(n0 + nn) * ldb + kt * 16 + (k4 << 2));
            }
        }
    };
    auto sts = [&](int buf) {
        uint32_t* Ah = smu + AHI0 + buf * ASTG;
        uint32_t* Al = smu + ALO0 + buf * ASTG;
        uint32_t* Bh = smu + BHI0 + buf * BSTG;
        uint32_t* Bl = smu + BLO0 + buf * BSTG;
#pragma unroll
        for (int it = 0; it < 2; ++it) {
            int idx = tid + (it << 8);
            float va[4] = {ra[it].x, ra[it].y, ra[it].z, ra[it].w};
            float vb[4] = {rb[it].x, rb[it].y, rb[it].z, rb[it].w};
            uint32_t hA[4], lA[4], hB[4], lB[4];
#pragma unroll
            for (int c = 0; c < 4; ++c) {
                hA[c] = tf32_hi(va[c]);
                lA[c] = __float_as_uint(va[c] - __uint_as_float(hA[c]));
                hB[c] = tf32_hi(vb[c]);
                lB[c] = __float_as_uint(vb[c] - __uint_as_float(hB[c]));
            }
            if (A_KM) {
                int kk = idx >> 5, m4 = idx & 31;
                int s = kk >> 3, kh = (kk & 7) >> 2, kq = kk & 3;
#pragma unroll
                for (int c = 0; c < 4; ++c) {
                    int m = (m4 << 2) + c;
                    int o = s * 1060 + (m >> 4) * 132 +
                            (((m & 7) << 2) + kq) * 4 + ((m >> 3) & 1) +
                            (kh << 1);
                    Ah[o] = hA[c];
                    Al[o] = lA[c];
                }
            } else {
                int mm = idx >> 2, k4 = idx & 3;
                int s = k4 >> 1, kh = k4 & 1;
                int mt = mm >> 4, reg = ((mm >> 3) & 1) + (kh << 1);
#pragma unroll
                for (int c = 0; c < 4; ++c) {
                    int o = s * 1060 + mt * 132 + (((mm & 7) << 2) + c) * 4 + reg;
                    Ah[o] = hA[c];
                    Al[o] = lA[c];
                }
            }
            if (B_KN) {
                int kk = idx >> 5, n4 = idx & 31;
                int s = kk >> 3, kh = (kk & 7) >> 2, kq = kk & 3;
#pragma unroll
                for (int c = 0; c < 4; ++c) {
                    int n = (n4 << 2) + c;
                    int o = s * 1058 + (n >> 3) * 66 +
                            (((n & 7) << 2) + kq) * 2 + kh;
                    Bh[o] = hB[c];
                    Bl[o] = lB[c];
                }
            } else {
                int nn = idx >> 2, k4 = idx & 3;
                int s = k4 >> 1, kh = k4 & 1, nt = nn >> 3;
#pragma unroll
                for (int c = 0; c < 4; ++c) {
                    int o = s * 1058 + nt * 66 + (((nn & 7) << 2) + c) * 2 + kh;
                    Bh[o] = hB[c];
                    Bl[o] = lB[c];
                }
            }
        }
    };
    auto compute = [&](int buf) {
        const uint32_t* Ah = smu + AHI0 + buf * ASTG;
        const uint32_t* Al = smu + ALO0 + buf * ASTG;
        const uint32_t* Bh = smu + BHI0 + buf * BSTG;
        const uint32_t* Bl = smu + BLO0 + buf * BSTG;
#pragma unroll
        for (int s = 0; s < 2; ++s) {
            uint32_t ah[4][4], al[4][4], bh[2], bl[2];
#pragma unroll
            for (int i = 0; i < 4; ++i) {
                const int o = s * 1060 + ((wm << 2) + i) * 132 + (lane << 2);
                *reinterpret_cast<uint4*>(ah[i]) =
                    *reinterpret_cast<const uint4*>(Ah + o);
                *reinterpret_cast<uint4*>(al[i]) =
                    *reinterpret_cast<const uint4*>(Al + o);
            }
#pragma unroll
            for (int j = 0; j < 4; ++j) {
                const int o = s * 1058 + ((wn << 2) + j) * 66 + (lane << 1);
                *reinterpret_cast<uint2*>(bh) =
                    *reinterpret_cast<const uint2*>(Bh + o);
                *reinterpret_cast<uint2*>(bl) =
                    *reinterpret_cast<const uint2*>(Bl + o);
#pragma unroll
                for (int i = 0; i < 4; ++i) {
                    mma8(acc[i][j], ah[i], bh);
                    mma8(acc[i][j], ah[i], bl);
                    mma8(acc[i][j], al[i], bh);
                }
            }
        }
    };

    ldg(0);
    sts(0);
    __syncthreads();
    const int nt = K >> 4;
    for (int t = 0; t < nt; ++t) {
        if (t + 1 < nt) ldg(t + 1);
        compute(t & 1);
        if (t + 1 < nt) sts((t + 1) & 1);  // other buffer: no conflict
        __syncthreads();
    }

    const int r = lane >> 2, cq = (lane & 3) << 1;
    float* Cb = C + (size_t)blockIdx.z * cB;
#pragma unroll
    for (int i = 0; i < 4; ++i) {
#pragma unroll
        for (int j = 0; j < 4; ++j) {
            const int row = m0 + (wm << 6) + (i << 4) + r;
            const int col = n0 + (wn << 5) + (j << 3) + cq;
            float o0 = acc[i][j][0], o1 = acc[i][j][1];
            float o2 = acc[i][j][2], o3 = acc[i][j][3];
            if (HAS_BIAS) {
                float b0 = bias[col], b1 = bias[col + 1];
                o0 += b0; o1 += b1; o2 += b0; o3 += b1;
            }
            *reinterpret_cast<float2*>(Cb + (size_t)row * Nn + col) =
                make_float2(o0, o1);
            *reinterpret_cast<float2*>(Cb + (size_t)(row + 8) * Nn + col) =
                make_float2(o2, o3);
        }
    }
}

// ---------------------------------------------------------------------------
// s[b][e] = sum_n x[b][n][e]
// ---------------------------------------------------------------------------
__global__ void __launch_bounds__(256)
colsum_kernel(const float* __restrict__ x, float* __restrict__ s) {
    const int e = blockIdx.x * 256 + threadIdx.x;
    const int b = blockIdx.y;
    const float* p = x + (size_t)b * N_ * D_ + e;
    float a0 = 0.f, a1 = 0.f, a2 = 0.f, a3 = 0.f;
    for (int n = 0; n < N_; n += 4) {
        a0 += p[(size_t)n * D_];
        a1 += p[(size_t)(n + 1) * D_];
        a2 += p[(size_t)(n + 2) * D_];
        a3 += p[(size_t)(n + 3) * D_];
    }
    s[b * D_ + e] = (a0 + a1) + (a2 + a3);
}

// u[b][e] = Wq[e].s[b] ;  w'[b][f] = Wk[f].s[b] + N*bk[f]
__global__ void __launch_bounds__(256)
gemv_kernel(const float* __restrict__ Wq, const float* __restrict__ Wk,
            const float* __restrict__ bk, const float* __restrict__ s,
            float* __restrict__ u, float* __restrict__ w) {
    const int wg = blockIdx.x * 8 + (threadIdx.x >> 5);
    const int lane = threadIdx.x & 31;
    const int b = wg >> 11;           // 2048 outputs per batch
    const int o = wg & 2047;
    const bool is_u = o < 1024;
    const int row = is_u ? o : o - 1024;
    const float* W = (is_u ? Wq : Wk) + (size_t)row * D_;
    const float* sb = s + b * D_;
    float acc = 0.f;
#pragma unroll
    for (int i = 0; i < 32; ++i) acc += W[lane + (i << 5)] * sb[lane + (i << 5)];
#pragma unroll
    for (int off = 16; off; off >>= 1)
        acc += __shfl_xor_sync(0xffffffffu, acc, off);
    if (lane == 0) {
        if (is_u) u[b * D_ + row] = acc;
        else      w[b * D_ + row] = acc + (float)N_ * bk[row];
    }
}

// ---------------------------------------------------------------------------
// softmax with fused rank-1 corrections:
// logit[b][e][f] = L + u[b][e]*bk[f] + bq[e]*w'[b][f]; softmax over f, inplace
// ---------------------------------------------------------------------------
__global__ void __launch_bounds__(256)
softmax_fused(float* __restrict__ L, const float* __restrict__ u,
              const float* __restrict__ w, const float* __restrict__ bq,
              const float* __restrict__ bk) {
    const int row = blockIdx.x;
    const int b = row >> 10, e = row & 1023;
    float* p = L + (size_t)row * 1024;
    const float uu = u[b * D_ + e];
    const float bb = bq[e];
    const float* wb = w + b * D_;
    const int t = threadIdx.x;
    const int lane = t & 31, wid = t >> 5;
    __shared__ float red[8];

    float v[4];
#pragma unroll
    for (int i = 0; i < 4; ++i) {
        const int f = t + (i << 8);
        v[i] = p[f] + uu * bk[f] + bb * wb[f];
    }

    float m = fmaxf(fmaxf(v[0], v[1]), fmaxf(v[2], v[3]));
#pragma unroll
    for (int o = 16; o; o >>= 1) m = fmaxf(m, __shfl_xor_sync(0xffffffffu, m, o));
    if (lane == 0) red[wid] = m;
    __syncthreads();
    if (t < 32) {
        float x = (t < 8) ? red[t] : -3.4e38f;
#pragma unroll
        for (int o = 4; o; o >>= 1) x = fmaxf(x, __shfl_xor_sync(0xffffffffu, x, o));
        if (t == 0) red[0] = x;
    }
    __syncthreads();
    m = red[0];
    __syncthreads();

    float ssum = 0.f;
#pragma unroll
    for (int i = 0; i < 4; ++i) {
        v[i] = expf(v[i] - m);
        ssum += v[i];
    }
#pragma unroll
    for (int o = 16; o; o >>= 1) ssum += __shfl_xor_sync(0xffffffffu, ssum, o);
    if (lane == 0) red[wid] = ssum;
    __syncthreads();
    if (t < 32) {
        float x = (t < 8) ? red[t] : 0.f;
#pragma unroll
        for (int o = 4; o; o >>= 1) x += __shfl_xor_sync(0xffffffffu, x, o);
        if (t == 0) red[0] = x;
    }
    __syncthreads();
    const float inv = 1.0f / red[0];
#pragma unroll
    for (int i = 0; i < 4; ++i) p[t + (i << 8)] = v[i] * inv;
}

extern "C" void kernel_launch(void* const* d_in, const int* in_sizes, int n_in,
                              void* d_out, int out_size) {
    const float* x  = (const float*)d_in[0];
    const float* Wq = (const float*)d_in[1];
    const float* bq = (const float*)d_in[2];
    const float* Wk = (const float*)d_in[3];
    const float* bk = (const float*)d_in[4];
    const float* Wv = (const float*)d_in[5];
    const float* bv = (const float*)d_in[6];
    float* out = (float*)d_out;

    float *v, *G, *T1, *L, *s, *u, *w;
    cudaGetSymbolAddress((void**)&v, g_v);
    cudaGetSymbolAddress((void**)&G, g_G);
    cudaGetSymbolAddress((void**)&T1, g_T1);
    cudaGetSymbolAddress((void**)&L, g_L);
    cudaGetSymbolAddress((void**)&s, g_s);
    cudaGetSymbolAddress((void**)&u, g_u);
    cudaGetSymbolAddress((void**)&w, g_w);

    cudaFuncSetAttribute(mma_gemm<false, false, true>,
                         cudaFuncAttributeMaxDynamicSharedMemorySize, SMEM_BYTES);
    cudaFuncSetAttribute(mma_gemm<true, true, false>,
                         cudaFuncAttributeMaxDynamicSharedMemorySize, SMEM_BYTES);
    cudaFuncSetAttribute(mma_gemm<false, false, false>,
                         cudaFuncAttributeMaxDynamicSharedMemorySize, SMEM_BYTES);
    cudaFuncSetAttribute(mma_gemm<false, true, false>,
                         cudaFuncAttributeMaxDynamicSharedMemorySize, SMEM_BYTES);

    const dim3 blk(256);

    // v = x @ Wv^T + bv      [32768,1024] x [1024,1024]
    mma_gemm<false, false, true><<<dim3(8, 256, 1), blk, SMEM_BYTES>>>(
        x, Wv, bv, v, B_ * N_, D_, D_, D_, D_, 0, 0, 0);

    // s = x^T 1 ; u = Wq s ; w' = Wk s + N bk
    colsum_kernel<<<dim3(4, 8), 256>>>(x, s);
    gemv_kernel<<<2048, 256>>>(Wq, Wk, bk, s, u, w);

    // G[b] = x[b]^T x[b]     M=N=1024, K=4096
    mma_gemm<true, true, false><<<dim3(8, 8, B_), blk, SMEM_BYTES>>>(
        x, x, nullptr, G, D_, D_, N_, D_, D_,
        (size_t)N_ * D_, (size_t)N_ * D_, (size_t)D_ * D_);

    // T1[b] = G[b] @ Wk^T    M=N=K=1024
    mma_gemm<false, false, false><<<dim3(8, 8, B_), blk, SMEM_BYTES>>>(
        G, Wk, nullptr, T1, D_, D_, D_, D_, D_,
        (size_t)D_ * D_, 0, (size_t)D_ * D_);

    // L[b] = Wq @ T1[b]      M=N=K=1024
    mma_gemm<false, true, false><<<dim3(8, 8, B_), blk, SMEM_BYTES>>>(
        Wq, T1, nullptr, L, D_, D_, D_, D_, D_,
        0, (size_t)D_ * D_, (size_t)D_ * D_);

    // softmax with rank-1 corrections, in place -> attn
    softmax_fused<<<B_ * D_, 256>>>(L, u, w, bq, bk);

    // out[b] = v[b] @ attn[b]   M=4096, N=1024, K=1024
    mma_gemm<false, true, false><<<dim3(8, 32, B_), blk, SMEM_BYTES>>>(
        v, L, nullptr, out, N_, D_, D_, D_, D_,
        (size_t)N_ * D_, (size_t)D_ * D_, (size_t)N_ * D_);
}

// round 8
// speedup vs baseline: 2.7131x; 1.4541x over previous
#include <cuda_runtime.h>
#include <cuda_fp16.h>
#include <cstdint>

#define B_   8
#define N_   4096
#define D_   1024

// scratch (device globals; no allocations allowed)
__device__ float g_v [(size_t)B_ * N_ * D_];   // v projection      128 MB
__device__ float g_G [(size_t)B_ * D_ * D_];   // G = x^T x          32 MB
__device__ float g_T1[(size_t)B_ * D_ * D_];   // T1 = G Wk^T        32 MB
__device__ float g_L [(size_t)B_ * D_ * D_];   // logits -> attn     32 MB
__device__ float g_s [(size_t)B_ * D_];        // s = x^T 1
__device__ float g_u [(size_t)B_ * D_];        // u = Wq s
__device__ float g_w [(size_t)B_ * D_];        // w' = Wk s + N*bk

__device__ __forceinline__ void mma16(float* c, const uint32_t* a,
                                      const uint32_t* b) {
    asm("mma.sync.aligned.m16n8k16.row.col.f32.f16.f16.f32 "
        "{%0,%1,%2,%3}, {%4,%5,%6,%7}, {%8,%9}, {%0,%1,%2,%3};"
        : "+f"(c[0]), "+f"(c[1]), "+f"(c[2]), "+f"(c[3])
        : "r"(a[0]), "r"(a[1]), "r"(a[2]), "r"(a[3]), "r"(b[0]), "r"(b[1]));
}

// split x = hi + lo, both fp16 (11-bit mantissa each -> ~22-bit coverage,
// same residual as 3xTF32 but m16n8k16 does 2x MACs per instruction)
__device__ __forceinline__ void split_h(float x, uint16_t& h, uint16_t& l) {
    __half hh = __float2half_rn(x);
    float hf = __half2float(hh);
    h = __half_as_ushort(hh);
    l = __half_as_ushort(__float2half_rn(x - hf));
}
__device__ __forceinline__ uint32_t pack2h(uint16_t lo, uint16_t hi) {
    return (uint32_t)lo | ((uint32_t)hi << 16);
}

// ---------------------------------------------------------------------------
// FP16 (3x split) mma.sync m16n8k16 GEMM: C[M,N] = A * B^T (+bias)
//   A_KM=false: A stored [M,K] (k contig), true: [K,M] (m contig)
//   B_KN=false: B stored [N,K] (k contig), true: [K,N] (n contig)
// CTA 128x128, 256 threads, 8 warps (grid 2x4), warp tile 64x32.
// K-stage 32 (2 k16-steps), double-buffered; hi/lo split once at store time.
// 2 CTAs/SM. Fragment-order SMEM, words are f16x2 pairs:
//   A: word idx = ks*1060 + mt*132 + lane*4 + reg   (mt<8, reg<4)
//   B: word idx = ks*1058 + nt*66  + lane*2 + reg   (nt<16, reg<2)
// element (row r 0..15 of m-tile, k 0..15): reg=(r>>3)+((k>>3)<<1),
//   lane=(r&7)*4+((k&7)>>1), half=k&1.   B: reg=k>>3, lane=(n&7)*4+((k&7)>>1).
// Regions: Ahi[2 buf] | Alo[2 buf] | Bhi[2 buf] | Blo[2 buf]
// ---------------------------------------------------------------------------
constexpr int ASTG = 2120, BSTG = 2116;
constexpr int AHI0 = 0;
constexpr int ALO0 = 2 * ASTG;
constexpr int BHI0 = 4 * ASTG;
constexpr int BLO0 = 4 * ASTG + 2 * BSTG;
constexpr int SMEM_BYTES = (4 * ASTG + 4 * BSTG) * 4;  // 67,776 B

template <bool A_KM, bool B_KN, bool HAS_BIAS>
__global__ void __launch_bounds__(256, 2)
mma_gemm(const float* __restrict__ A, const float* __restrict__ Bm,
         const float* __restrict__ bias, float* __restrict__ C,
         int M, int Nn, int K, int lda, int ldb,
         size_t aB, size_t bB, size_t cB) {
    extern __shared__ float sm[];
    uint32_t* smu = reinterpret_cast<uint32_t*>(sm);
    const int tid = threadIdx.x;
    const int lane = tid & 31, wid = tid >> 5;
    const int wm = wid & 1, wn = wid >> 1;  // warp grid 2(M) x 4(N)
    const float* Ab = A + (size_t)blockIdx.z * aB;
    const float* Bb = Bm + (size_t)blockIdx.z * bB;
    const int m0 = blockIdx.y * 128;
    const int n0 = blockIdx.x * 128;

    float acc[4][4][4];
#pragma unroll
    for (int i = 0; i < 4; ++i)
#pragma unroll
        for (int j = 0; j < 4; ++j)
#pragma unroll
            for (int e = 0; e < 4; ++e) acc[i][j][e] = 0.f;

    // per stage: A tile 128x32 f32 = 1024 float4; 256 threads -> 4 each
    float4 ra[4], rb[4];
    auto ldg = [&](int kt) {
#pragma unroll
        for (int it = 0; it < 4; ++it) {
            int idx = tid + (it << 8);
            if (A_KM) {
                int kk = idx >> 5, m4 = idx & 31;
                ra[it] = *reinterpret_cast<const float4*>(
                    Ab + (size_t)(kt * 32 + kk) * lda + m0 + (m4 << 2));
            } else {
                int mm = idx >> 3, k4 = idx & 7;
                ra[it] = *reinterpret_cast<const float4*>(
                    Ab + (size_t)(m0 + mm) * lda + kt * 32 + (k4 << 2));
            }
            if (B_KN) {
                int kk = idx >> 5, n4 = idx & 31;
                rb[it] = *reinterpret_cast<const float4*>(
                    Bb + (size_t)(kt * 32 + kk) * ldb + n0 + (n4 << 2));
            } else {
                int nn = idx >> 3, k4 = idx & 7;
                rb[it] = *reinterpret_cast<const float4*>(
                    Bb + (size_t)(n0 + nn) * ldb + kt * 32 + (k4 << 2));
            }
        }
    };
    auto sts = [&](int buf) {
        uint32_t* Ah = smu + AHI0 + buf * ASTG;
        uint32_t* Al = smu + ALO0 + buf * ASTG;
        uint32_t* Bh = smu + BHI0 + buf * BSTG;
        uint32_t* Bl = smu + BLO0 + buf * BSTG;
#pragma unroll
        for (int it = 0; it < 4; ++it) {
            int idx = tid + (it << 8);
            float va[4] = {ra[it].x, ra[it].y, ra[it].z, ra[it].w};
            float vb[4] = {rb[it].x, rb[it].y, rb[it].z, rb[it].w};
            uint16_t hA[4], lA[4], hB[4], lB[4];
#pragma unroll
            for (int c = 0; c < 4; ++c) {
                split_h(va[c], hA[c], lA[c]);
                split_h(vb[c], hB[c], lB[c]);
            }
            if (A_KM) {
                // va[c] is element (k = kk, m = 4*m4 + c): u16 scatter
                int kk = idx >> 5, m4 = idx & 31;
                int ks = kk >> 4, k = kk & 15;
                int half = k & 1;
                int kreg = (k >> 3) << 1, ksel = (k & 7) >> 1;
                uint16_t* Ah16 = reinterpret_cast<uint16_t*>(Ah);
                uint16_t* Al16 = reinterpret_cast<uint16_t*>(Al);
#pragma unroll
                for (int c = 0; c < 4; ++c) {
                    int m = (m4 << 2) + c;
                    int rr = m & 15, mt = m >> 4;
                    int o = ks * 1060 + mt * 132 +
                            (((rr & 7) << 2) + ksel) * 4 + (rr >> 3) + kreg;
                    Ah16[(o << 1) + half] = hA[c];
                    Al16[(o << 1) + half] = lA[c];
                }
            } else {
                // va = 4 consecutive k at (row mm, k0=4*k4): 2 packed words
                int mm = idx >> 3, k4 = idx & 7;
                int k0 = k4 << 2;
                int ks = k0 >> 4, kk = k0 & 15;
                int rr = mm & 15, mt = mm >> 4;
                int reg = (rr >> 3) + ((kk >> 3) << 1);
                int o = ks * 1060 + mt * 132 +
                        (((rr & 7) << 2) + ((kk & 7) >> 1)) * 4 + reg;
                Ah[o] = pack2h(hA[0], hA[1]);
                Ah[o + 4] = pack2h(hA[2], hA[3]);
                Al[o] = pack2h(lA[0], lA[1]);
                Al[o + 4] = pack2h(lA[2], lA[3]);
            }
            if (B_KN) {
                int kk = idx >> 5, n4 = idx & 31;
                int ks = kk >> 4, k = kk & 15;
                int half = k & 1;
                int reg = k >> 3, ksel = (k & 7) >> 1;
                uint16_t* Bh16 = reinterpret_cast<uint16_t*>(Bh);
                uint16_t* Bl16 = reinterpret_cast<uint16_t*>(Bl);
#pragma unroll
                for (int c = 0; c < 4; ++c) {
                    int n = (n4 << 2) + c;
                    int nt = n >> 3;
                    int o = ks * 1058 + nt * 66 +
                            (((n & 7) << 2) + ksel) * 2 + reg;
                    Bh16[(o << 1) + half] = hB[c];
                    Bl16[(o << 1) + half] = lB[c];
                }
            } else {
                int nn = idx >> 3, k4 = idx & 7;
                int k0 = k4 << 2;
                int ks = k0 >> 4, kk = k0 & 15;
                int nt = nn >> 3;
                int reg = kk >> 3;
                int o = ks * 1058 + nt * 66 +
                        (((nn & 7) << 2) + ((kk & 7) >> 1)) * 2 + reg;
                Bh[o] = pack2h(hB[0], hB[1]);
                Bh[o + 2] = pack2h(hB[2], hB[3]);
                Bl[o] = pack2h(lB[0], lB[1]);
                Bl[o + 2] = pack2h(lB[2], lB[3]);
            }
        }
    };
    auto compute = [&](int buf) {
        const uint32_t* Ah = smu + AHI0 + buf * ASTG;
        const uint32_t* Al = smu + ALO0 + buf * ASTG;
        const uint32_t* Bh = smu + BHI0 + buf * BSTG;
        const uint32_t* Bl = smu + BLO0 + buf * BSTG;
#pragma unroll
        for (int ks = 0; ks < 2; ++ks) {
            uint32_t bh[4][2], bl[4][2];
#pragma unroll
            for (int j = 0; j < 4; ++j) {
                const int o = ks * 1058 + ((wn << 2) + j) * 66 + (lane << 1);
                *reinterpret_cast<uint2*>(bh[j]) =
                    *reinterpret_cast<const uint2*>(Bh + o);
                *reinterpret_cast<uint2*>(bl[j]) =
                    *reinterpret_cast<const uint2*>(Bl + o);
            }
#pragma unroll
            for (int i = 0; i < 4; ++i) {
                uint32_t ah[4], al[4];
                const int o = ks * 1060 + ((wm << 2) + i) * 132 + (lane << 2);
                *reinterpret_cast<uint4*>(ah) =
                    *reinterpret_cast<const uint4*>(Ah + o);
                *reinterpret_cast<uint4*>(al) =
                    *reinterpret_cast<const uint4*>(Al + o);
#pragma unroll
                for (int j = 0; j < 4; ++j) {
                    mma16(acc[i][j], ah, bh[j]);
                    mma16(acc[i][j], ah, bl[j]);
                    mma16(acc[i][j], al, bh[j]);
                }
            }
        }
    };

    ldg(0);
    sts(0);
    __syncthreads();
    const int nt = K >> 5;
    for (int t = 0; t < nt; ++t) {
        if (t + 1 < nt) ldg(t + 1);
        compute(t & 1);
        if (t + 1 < nt) sts((t + 1) & 1);  // other buffer: no conflict
        __syncthreads();
    }

    const int r = lane >> 2, cq = (lane & 3) << 1;
    float* Cb = C + (size_t)blockIdx.z * cB;
#pragma unroll
    for (int i = 0; i < 4; ++i) {
#pragma unroll
        for (int j = 0; j < 4; ++j) {
            const int row = m0 + (wm << 6) + (i << 4) + r;
            const int col = n0 + (wn << 5) + (j << 3) + cq;
            float o0 = acc[i][j][0], o1 = acc[i][j][1];
            float o2 = acc[i][j][2], o3 = acc[i][j][3];
            if (HAS_BIAS) {
                float b0 = bias[col], b1 = bias[col + 1];
                o0 += b0; o1 += b1; o2 += b0; o3 += b1;
            }
            *reinterpret_cast<float2*>(Cb + (size_t)row * Nn + col) =
                make_float2(o0, o1);
            *reinterpret_cast<float2*>(Cb + (size_t)(row + 8) * Nn + col) =
                make_float2(o2, o3);
        }
    }
}

// ---------------------------------------------------------------------------
// s[b][e] = sum_n x[b][n][e]
// ---------------------------------------------------------------------------
__global__ void __launch_bounds__(256)
colsum_kernel(const float* __restrict__ x, float* __restrict__ s) {
    const int e = blockIdx.x * 256 + threadIdx.x;
    const int b = blockIdx.y;
    const float* p = x + (size_t)b * N_ * D_ + e;
    float a0 = 0.f, a1 = 0.f, a2 = 0.f, a3 = 0.f;
    for (int n = 0; n < N_; n += 4) {
        a0 += p[(size_t)n * D_];
        a1 += p[(size_t)(n + 1) * D_];
        a2 += p[(size_t)(n + 2) * D_];
        a3 += p[(size_t)(n + 3) * D_];
    }
    s[b * D_ + e] = (a0 + a1) + (a2 + a3);
}

// u[b][e] = Wq[e].s[b] ;  w'[b][f] = Wk[f].s[b] + N*bk[f]
__global__ void __launch_bounds__(256)
gemv_kernel(const float* __restrict__ Wq, const float* __restrict__ Wk,
            const float* __restrict__ bk, const float* __restrict__ s,
            float* __restrict__ u, float* __restrict__ w) {
    const int wg = blockIdx.x * 8 + (threadIdx.x >> 5);
    const int lane = threadIdx.x & 31;
    const int b = wg >> 11;           // 2048 outputs per batch
    const int o = wg & 2047;
    const bool is_u = o < 1024;
    const int row = is_u ? o : o - 1024;
    const float* W = (is_u ? Wq : Wk) + (size_t)row * D_;
    const float* sb = s + b * D_;
    float acc = 0.f;
#pragma unroll
    for (int i = 0; i < 32; ++i) acc += W[lane + (i << 5)] * sb[lane + (i << 5)];
#pragma unroll
    for (int off = 16; off; off >>= 1)
        acc += __shfl_xor_sync(0xffffffffu, acc, off);
    if (lane == 0) {
        if (is_u) u[b * D_ + row] = acc;
        else      w[b * D_ + row] = acc + (float)N_ * bk[row];
    }
}

// ---------------------------------------------------------------------------
// softmax with fused rank-1 corrections:
// logit[b][e][f] = L + u[b][e]*bk[f] + bq[e]*w'[b][f]; softmax over f, inplace
// ---------------------------------------------------------------------------
__global__ void __launch_bounds__(256)
softmax_fused(float* __restrict__ L, const float* __restrict__ u,
              const float* __restrict__ w, const float* __restrict__ bq,
              const float* __restrict__ bk) {
    const int row = blockIdx.x;
    const int b = row >> 10, e = row & 1023;
    float* p = L + (size_t)row * 1024;
    const float uu = u[b * D_ + e];
    const float bb = bq[e];
    const float* wb = w + b * D_;
    const int t = threadIdx.x;
    const int lane = t & 31, wid = t >> 5;
    __shared__ float red[8];

    float v[4];
#pragma unroll
    for (int i = 0; i < 4; ++i) {
        const int f = t + (i << 8);
        v[i] = p[f] + uu * bk[f] + bb * wb[f];
    }

    float m = fmaxf(fmaxf(v[0], v[1]), fmaxf(v[2], v[3]));
#pragma unroll
    for (int o = 16; o; o >>= 1) m = fmaxf(m, __shfl_xor_sync(0xffffffffu, m, o));
    if (lane == 0) red[wid] = m;
    __syncthreads();
    if (t < 32) {
        float x = (t < 8) ? red[t] : -3.4e38f;
#pragma unroll
        for (int o = 4; o; o >>= 1) x = fmaxf(x, __shfl_xor_sync(0xffffffffu, x, o));
        if (t == 0) red[0] = x;
    }
    __syncthreads();
    m = red[0];
    __syncthreads();

    float ssum = 0.f;
#pragma unroll
    for (int i = 0; i < 4; ++i) {
        v[i] = expf(v[i] - m);
        ssum += v[i];
    }
#pragma unroll
    for (int o = 16; o; o >>= 1) ssum += __shfl_xor_sync(0xffffffffu, ssum, o);
    if (lane == 0) red[wid] = ssum;
    __syncthreads();
    if (t < 32) {
        float x = (t < 8) ? red[t] : 0.f;
#pragma unroll
        for (int o = 4; o; o >>= 1) x += __shfl_xor_sync(0xffffffffu, x, o);
        if (t == 0) red[0] = x;
    }
    __syncthreads();
    const float inv = 1.0f / red[0];
#pragma unroll
    for (int i = 0; i < 4; ++i) p[t + (i << 8)] = v[i] * inv;
}

extern "C" void kernel_launch(void* const* d_in, const int* in_sizes, int n_in,
                              void* d_out, int out_size) {
    const float* x  = (const float*)d_in[0];
    const float* Wq = (const float*)d_in[1];
    const float* bq = (const float*)d_in[2];
    const float* Wk = (const float*)d_in[3];
    const float* bk = (const float*)d_in[4];
    const float* Wv = (const float*)d_in[5];
    const float* bv = (const float*)d_in[6];
    float* out = (float*)d_out;

    float *v, *G, *T1, *L, *s, *u, *w;
    cudaGetSymbolAddress((void**)&v, g_v);
    cudaGetSymbolAddress((void**)&G, g_G);
    cudaGetSymbolAddress((void**)&T1, g_T1);
    cudaGetSymbolAddress((void**)&L, g_L);
    cudaGetSymbolAddress((void**)&s, g_s);
    cudaGetSymbolAddress((void**)&u, g_u);
    cudaGetSymbolAddress((void**)&w, g_w);

    cudaFuncSetAttribute(mma_gemm<false, false, true>,
                         cudaFuncAttributeMaxDynamicSharedMemorySize, SMEM_BYTES);
    cudaFuncSetAttribute(mma_gemm<true, true, false>,
                         cudaFuncAttributeMaxDynamicSharedMemorySize, SMEM_BYTES);
    cudaFuncSetAttribute(mma_gemm<false, false, false>,
                         cudaFuncAttributeMaxDynamicSharedMemorySize, SMEM_BYTES);
    cudaFuncSetAttribute(mma_gemm<false, true, false>,
                         cudaFuncAttributeMaxDynamicSharedMemorySize, SMEM_BYTES);

    const dim3 blk(256);

    // v = x @ Wv^T + bv      [32768,1024] x [1024,1024]
    mma_gemm<false, false, true><<<dim3(8, 256, 1), blk, SMEM_BYTES>>>(
        x, Wv, bv, v, B_ * N_, D_, D_, D_, D_, 0, 0, 0);

    // s = x^T 1 ; u = Wq s ; w' = Wk s + N bk
    colsum_kernel<<<dim3(4, 8), 256>>>(x, s);
    gemv_kernel<<<2048, 256>>>(Wq, Wk, bk, s, u, w);

    // G[b] = x[b]^T x[b]     M=N=1024, K=4096
    mma_gemm<true, true, false><<<dim3(8, 8, B_), blk, SMEM_BYTES>>>(
        x, x, nullptr, G, D_, D_, N_, D_, D_,
        (size_t)N_ * D_, (size_t)N_ * D_, (size_t)D_ * D_);

    // T1[b] = G[b] @ Wk^T    M=N=K=1024
    mma_gemm<false, false, false><<<dim3(8, 8, B_), blk, SMEM_BYTES>>>(
        G, Wk, nullptr, T1, D_, D_, D_, D_, D_,
        (size_t)D_ * D_, 0, (size_t)D_ * D_);

    // L[b] = Wq @ T1[b]      M=N=K=1024
    mma_gemm<false, true, false><<<dim3(8, 8, B_), blk, SMEM_BYTES>>>(
        Wq, T1, nullptr, L, D_, D_, D_, D_, D_,
        0, (size_t)D_ * D_, (size_t)D_ * D_);

    // softmax with rank-1 corrections, in place -> attn
    softmax_fused<<<B_ * D_, 256>>>(L, u, w, bq, bk);

    // out[b] = v[b] @ attn[b]   M=4096, N=1024, K=1024
    mma_gemm<false, true, false><<<dim3(8, 32, B_), blk, SMEM_BYTES>>>(
        v, L, nullptr, out, N_, D_, D_, D_, D_,
        (size_t)N_ * D_, (size_t)D_ * D_, (size_t)N_ * D_);
}